// round 1
// baseline (speedup 1.0000x reference)
#include <cuda_runtime.h>
#include <cstddef>

// Problem dims (fixed by setup_inputs)
#define BS 4
#define NF 8
#define NT 256
#define DIN 64
#define NH 8
#define DOUT 64
#define BF (BS*NF)          // 32
#define NK (NH*DIN)         // 512

// Scratch (no allocations allowed)
__device__ float g_Q[BF * NT * NH * 2];        // [bf][t][h][e]  131072
__device__ float g_K[BF * NT * NH * 2];        // 131072
__device__ float g_vals[BF * NT * NK];         // [bf][t][h*64+d] 4194304 (16MB)

// ---------------------------------------------------------------------------
// Kernel 1: Q/K projections. grid = BF*NT/4 blocks, 128 threads (4 warps).
// Each warp handles one (b,f,t); lanes 0..15 -> Q[he], lanes 16..31 -> K[he].
// ---------------------------------------------------------------------------
__global__ void qk_kernel(const float* __restrict__ X,
                          const float* __restrict__ Wq,
                          const float* __restrict__ Wk)
{
    int idx  = blockIdx.x * 4 + (threadIdx.x >> 5);   // [0, BF*NT)
    int lane = threadIdx.x & 31;
    int t_ft = idx & (NF * NT - 1);                   // f*T + t  (idx = b*2048 + f*256 + t)

    const float* x = X + (size_t)idx * DIN;
    const float* wbase = (lane < 16 ? Wq : Wk) + (size_t)t_ft * (DIN * 16) + (lane & 15);

    float acc = 0.f;
#pragma unroll 8
    for (int d = 0; d < DIN; d++)
        acc = fmaf(__ldg(&x[d]), __ldg(&wbase[d * 16]), acc);

    if (lane < 16) g_Q[(size_t)idx * 16 + lane] = acc;
    else           g_K[(size_t)idx * 16 + (lane - 16)] = acc;
}

// ---------------------------------------------------------------------------
// Kernel 2: fused scores -> softmax -> probs @ X.
// grid = BF * (NT/8) = 1024 blocks, 256 threads (8 warps, one t per warp).
// smem: Xs[256][64] | Ksm[8][256*2] | usm[256*2] | Psm[8 warps][256][12]
// ---------------------------------------------------------------------------
#define SM_XS   0
#define SM_KSM  16384
#define SM_USM  (16384 + 4096)
#define SM_PSM  (16384 + 4096 + 512)
#define SM_FLOATS (SM_PSM + 8*256*12)   // 45568 floats = 182272 bytes

__global__ void attn_kernel(const float* __restrict__ X,
                            const float* __restrict__ ac,
                            const float* __restrict__ alpha,
                            const float* __restrict__ wkey,
                            const float* __restrict__ u)
{
    extern __shared__ float sm[];
    float* Xs  = sm + SM_XS;
    float* Ksm = sm + SM_KSM;
    float* usm = sm + SM_USM;
    float* Psm = sm + SM_PSM;

    int bf   = blockIdx.x >> 5;
    int f    = bf & (NF - 1);
    int t0   = (blockIdx.x & 31) << 3;
    int tid  = threadIdx.x;
    int lane = tid & 31;
    int w    = tid >> 5;

    // Stage X[bf] (64KB), K[bf] re-laid as [h][l*2+e], u[f]
    {
        const float4* Xg4 = (const float4*)(X + (size_t)bf * (NT * DIN));
        float4* Xs4 = (float4*)Xs;
        for (int i = tid; i < NT * DIN / 4; i += 256) Xs4[i] = __ldg(&Xg4[i]);

        const float* Kg = g_K + (size_t)bf * (NT * 16);
        for (int i = tid; i < NT * 16; i += 256) {
            float kv = Kg[i];
            int l = i >> 4, h = (i >> 1) & 7, e = i & 1;
            Ksm[h * 512 + l * 2 + e] = kv;
        }
        for (int i = tid; i < NT * 2; i += 256) usm[i] = __ldg(&u[f * (NT * 2) + i]);
    }
    __syncthreads();

    int t     = t0 + w;
    int idx_t = bf * NT + t;
    float alpha_f = __ldg(&alpha[f]);
    float a0 = __ldg(&wkey[f * 4 + 0]), b0 = __ldg(&wkey[f * 4 + 1]);
    float a1 = __ldg(&wkey[f * 4 + 2]), b1 = __ldg(&wkey[f * 4 + 3]);
    float v0 = -alpha_f;
    float* Pw = Psm + w * (256 * 12);

    // ---- scores + softmax for 8 heads of this t ----
    for (int h = 0; h < NH; h++) {
        const float* qp = g_Q + ((size_t)idx_t * 8 + h) * 2;
        const float* kp = g_K + ((size_t)idx_t * 8 + h) * 2;
        float q0 = __ldg(qp), q1 = __ldg(qp + 1);
        float kt0 = __ldg(kp), kt1 = __ldg(kp + 1);
        float v1 = 2.0f * alpha_f * __ldg(&ac[f * NH + h]);
        float qa0 = q0 + v0, qa1 = q1 + v1;
        float A = fmaf(qa0, a0, qa1 * a1);
        float B = fmaf(qa0, b0, qa1 * b1);

        const float* Kh = Ksm + h * 512;
        float s[8];
        float m = -3.4e38f;
#pragma unroll
        for (int j = 0; j < 8; j++) {
            int l = j * 32 + lane;
            float2 kv = *(const float2*)(Kh + l * 2);
            float2 uv = *(const float2*)(usm + l * 2);
            float r = (float)(l - t);
            float sc = r * fmaf(A, r, B);
            sc = fmaf(q0, kv.x, sc);
            sc = fmaf(q1, kv.y, sc);
            sc = fmaf(uv.x, kt0, sc);
            sc = fmaf(uv.y, kt1, sc);
            s[j] = sc;
            m = fmaxf(m, sc);
        }
#pragma unroll
        for (int o = 16; o; o >>= 1) m = fmaxf(m, __shfl_xor_sync(0xffffffffu, m, o));
        float sum = 0.f;
#pragma unroll
        for (int j = 0; j < 8; j++) { s[j] = __expf(s[j] - m); sum += s[j]; }
#pragma unroll
        for (int o = 16; o; o >>= 1) sum += __shfl_xor_sync(0xffffffffu, sum, o);
        float inv = 1.0f / sum;
#pragma unroll
        for (int j = 0; j < 8; j++)
            Pw[(j * 32 + lane) * 12 + h] = s[j] * inv;
    }
    __syncwarp();

    // ---- vals[t][h][d] = sum_l P[l][h] * X[l][d], d = lane*2, lane*2+1 ----
    float2 acc[8];
#pragma unroll
    for (int h = 0; h < 8; h++) { acc[h].x = 0.f; acc[h].y = 0.f; }
    int dlane = lane * 2;

#pragma unroll 4
    for (int l = 0; l < NT; l++) {
        float2 xv = *(const float2*)(Xs + l * 64 + dlane);
        float4 pA = *(const float4*)(Pw + l * 12);
        float4 pB = *(const float4*)(Pw + l * 12 + 4);
        acc[0].x = fmaf(pA.x, xv.x, acc[0].x);  acc[0].y = fmaf(pA.x, xv.y, acc[0].y);
        acc[1].x = fmaf(pA.y, xv.x, acc[1].x);  acc[1].y = fmaf(pA.y, xv.y, acc[1].y);
        acc[2].x = fmaf(pA.z, xv.x, acc[2].x);  acc[2].y = fmaf(pA.z, xv.y, acc[2].y);
        acc[3].x = fmaf(pA.w, xv.x, acc[3].x);  acc[3].y = fmaf(pA.w, xv.y, acc[3].y);
        acc[4].x = fmaf(pB.x, xv.x, acc[4].x);  acc[4].y = fmaf(pB.x, xv.y, acc[4].y);
        acc[5].x = fmaf(pB.y, xv.x, acc[5].x);  acc[5].y = fmaf(pB.y, xv.y, acc[5].y);
        acc[6].x = fmaf(pB.z, xv.x, acc[6].x);  acc[6].y = fmaf(pB.z, xv.y, acc[6].y);
        acc[7].x = fmaf(pB.w, xv.x, acc[7].x);  acc[7].y = fmaf(pB.w, xv.y, acc[7].y);
    }

    float* vout = g_vals + (size_t)idx_t * NK + dlane;
#pragma unroll
    for (int h = 0; h < 8; h++)
        *(float2*)(vout + h * 64) = acc[h];
}

// ---------------------------------------------------------------------------
// Kernel 3: out[t][o] = vals[t][:] @ W[f][:][o] + b[f][t][o]
// grid = BF * (NT/64) = 128 blocks, 256 threads. smem: VsT[512][68] (vals^T).
// ---------------------------------------------------------------------------
#define VPAD 68
#define SM3_FLOATS (NK * VPAD)   // 34816 floats = 139264 bytes

__global__ void out_kernel(const float* __restrict__ W,
                           const float* __restrict__ Bv,
                           float* __restrict__ Out)
{
    extern __shared__ float sm[];   // VsT[k][t_local], stride VPAD
    int bf  = blockIdx.x >> 2;
    int f   = bf & (NF - 1);
    int t0  = (blockIdx.x & 3) << 6;
    int tid = threadIdx.x;
    int lane = tid & 31;
    int w   = tid >> 5;

    // Transpose-load vals[t0..t0+63][0..511] -> VsT[k][t_local]
    for (int row = w; row < 64; row += 8) {
        const float* src = g_vals + ((size_t)(bf * NT + t0 + row)) * NK;
#pragma unroll
        for (int ph = 0; ph < 4; ph++) {
#pragma unroll
            for (int c = 0; c < 4; c++) {
                int k = ph * 128 + c * 32 + lane;     // lane-contiguous -> 4-way STS only
                sm[k * VPAD + row] = __ldg(&src[k]);
            }
        }
    }
    __syncthreads();

    int oc = (tid & 15) * 4;   // 4 output cols
    int tr = tid >> 4;         // 16 row-groups of 4 t
    const float* Wf = W + (size_t)f * (NK * DOUT) + oc;

    float acc[4][4];
#pragma unroll
    for (int i = 0; i < 4; i++)
#pragma unroll
        for (int j = 0; j < 4; j++) acc[i][j] = 0.f;

#pragma unroll 4
    for (int k = 0; k < NK; k++) {
        float4 w4 = __ldg((const float4*)(Wf + (size_t)k * DOUT));
        float4 v4 = *(const float4*)(sm + k * VPAD + tr * 4);
        acc[0][0] = fmaf(v4.x, w4.x, acc[0][0]); acc[0][1] = fmaf(v4.x, w4.y, acc[0][1]);
        acc[0][2] = fmaf(v4.x, w4.z, acc[0][2]); acc[0][3] = fmaf(v4.x, w4.w, acc[0][3]);
        acc[1][0] = fmaf(v4.y, w4.x, acc[1][0]); acc[1][1] = fmaf(v4.y, w4.y, acc[1][1]);
        acc[1][2] = fmaf(v4.y, w4.z, acc[1][2]); acc[1][3] = fmaf(v4.y, w4.w, acc[1][3]);
        acc[2][0] = fmaf(v4.z, w4.x, acc[2][0]); acc[2][1] = fmaf(v4.z, w4.y, acc[2][1]);
        acc[2][2] = fmaf(v4.z, w4.z, acc[2][2]); acc[2][3] = fmaf(v4.z, w4.w, acc[2][3]);
        acc[3][0] = fmaf(v4.w, w4.x, acc[3][0]); acc[3][1] = fmaf(v4.w, w4.y, acc[3][1]);
        acc[3][2] = fmaf(v4.w, w4.z, acc[3][2]); acc[3][3] = fmaf(v4.w, w4.w, acc[3][3]);
    }

#pragma unroll
    for (int i = 0; i < 4; i++) {
        int t = t0 + tr * 4 + i;
        float4 bb = __ldg((const float4*)(Bv + ((size_t)(f * NT + t)) * DOUT + oc));
        float4 r;
        r.x = acc[i][0] + bb.x;
        r.y = acc[i][1] + bb.y;
        r.z = acc[i][2] + bb.z;
        r.w = acc[i][3] + bb.w;
        *(float4*)(Out + ((size_t)(bf * NT + t)) * DOUT + oc) = r;
    }
}

// ---------------------------------------------------------------------------
extern "C" void kernel_launch(void* const* d_in, const int* in_sizes, int n_in,
                              void* d_out, int out_size)
{
    const float* X     = (const float*)d_in[0];
    const float* ac    = (const float*)d_in[1];
    const float* alpha = (const float*)d_in[2];
    const float* Wq    = (const float*)d_in[3];
    const float* Wk    = (const float*)d_in[4];
    const float* wkey  = (const float*)d_in[5];
    const float* u     = (const float*)d_in[6];
    const float* W     = (const float*)d_in[7];
    const float* Bv    = (const float*)d_in[8];
    float* Out = (float*)d_out;

    size_t smem2 = (size_t)SM_FLOATS * sizeof(float);   // 182272 B
    size_t smem3 = (size_t)SM3_FLOATS * sizeof(float);  // 139264 B
    cudaFuncSetAttribute(attn_kernel, cudaFuncAttributeMaxDynamicSharedMemorySize, (int)smem2);
    cudaFuncSetAttribute(out_kernel,  cudaFuncAttributeMaxDynamicSharedMemorySize, (int)smem3);

    qk_kernel<<<(BF * NT) / 4, 128>>>(X, Wq, Wk);
    attn_kernel<<<BF * (NT / 8), 256, smem2>>>(X, ac, alpha, wkey, u);
    out_kernel<<<BF * (NT / 64), 256, smem3>>>(W, Bv, Out);
}

// round 2
// speedup vs baseline: 1.6298x; 1.6298x over previous
#include <cuda_runtime.h>
#include <cstddef>

#define BS 4
#define NF 8
#define NT 256
#define DIN 64
#define NH 8
#define DOUT 64
#define BF (BS*NF)          // 32
#define NK (NH*DIN)         // 512

typedef unsigned long long u64;

// packed fp32x2 FMA: d = a*b + d (element-wise on 2 packed floats)
#define FFMA2(d,a,b) asm("fma.rn.f32x2 %0, %1, %2, %0;" : "+l"(d) : "l"(a), "l"(b))
// duplicate a float into both halves of an f32x2
#define DUP2(d,x)    asm("mov.b64 %0, {%1, %1};" : "=l"(d) : "r"(__float_as_uint(x)))

__device__ __forceinline__ float lo32(u64 v){ return __int_as_float((int)(v & 0xffffffffull)); }
__device__ __forceinline__ float hi32(u64 v){ return __int_as_float((int)(v >> 32)); }

// Scratch
__device__ float g_Q[BF * NT * NH * 2];   // [bf][t][h][e]
__device__ float g_K[BF * NT * NH * 2];
__device__ float g_vals[BF * NK * NT];    // TRANSPOSED: [bf][k][t], k = h*64+d

// ---------------------------------------------------------------------------
// Kernel 1: Q/K projections. grid = BF*NT/8, 256 threads. Warp per (b,f,t).
// lane = dq*4 + hq : dq in [0,8) covers d mod 8, hq in [0,4) covers he-quad.
// ---------------------------------------------------------------------------
__global__ void qk_kernel(const float* __restrict__ X,
                          const float* __restrict__ Wq,
                          const float* __restrict__ Wk)
{
    int idx  = blockIdx.x * 8 + (threadIdx.x >> 5);   // (b,f,t)
    int lane = threadIdx.x & 31;
    int t_ft = idx & (NF * NT - 1);

    const float* x = X + (size_t)idx * DIN;
    float x0 = __ldg(&x[lane]);
    float x1 = __ldg(&x[lane + 32]);

    int dq = lane >> 2;
    const float4* Wq4 = (const float4*)(Wq + (size_t)t_ft * (DIN * 16));
    const float4* Wk4 = (const float4*)(Wk + (size_t)t_ft * (DIN * 16));

    float4 aq = {0,0,0,0}, ak = {0,0,0,0};
#pragma unroll
    for (int i = 0; i < 8; i++) {
        int dsel = (i & 3) * 8 + dq;                 // d & 31
        float xv = __shfl_sync(0xffffffffu, (i < 4) ? x0 : x1, dsel);
        float4 wq = __ldg(&Wq4[i * 32 + lane]);      // coalesced 512B/warp
        float4 wk = __ldg(&Wk4[i * 32 + lane]);
        aq.x = fmaf(xv, wq.x, aq.x); aq.y = fmaf(xv, wq.y, aq.y);
        aq.z = fmaf(xv, wq.z, aq.z); aq.w = fmaf(xv, wq.w, aq.w);
        ak.x = fmaf(xv, wk.x, ak.x); ak.y = fmaf(xv, wk.y, ak.y);
        ak.z = fmaf(xv, wk.z, ak.z); ak.w = fmaf(xv, wk.w, ak.w);
    }
    // reduce over dq (lane bits 2..4)
#pragma unroll
    for (int off = 16; off >= 4; off >>= 1) {
        aq.x += __shfl_xor_sync(0xffffffffu, aq.x, off);
        aq.y += __shfl_xor_sync(0xffffffffu, aq.y, off);
        aq.z += __shfl_xor_sync(0xffffffffu, aq.z, off);
        aq.w += __shfl_xor_sync(0xffffffffu, aq.w, off);
        ak.x += __shfl_xor_sync(0xffffffffu, ak.x, off);
        ak.y += __shfl_xor_sync(0xffffffffu, ak.y, off);
        ak.z += __shfl_xor_sync(0xffffffffu, ak.z, off);
        ak.w += __shfl_xor_sync(0xffffffffu, ak.w, off);
    }
    if (lane < 4)                 *(float4*)(g_Q + (size_t)idx * 16 + lane * 4) = aq;
    else if (lane < 8)            *(float4*)(g_K + (size_t)idx * 16 + (lane - 4) * 4) = ak;
}

// ---------------------------------------------------------------------------
// Kernel 2: fused scores -> softmax -> probs @ X (FFMA2), vals out transposed.
// grid = BF*16 = 512 blocks, 512 threads (16 warps; warp w -> t = t0 + w).
// smem: Xp[128][64][2] paired | Ksm[8][512] | usm[512] | Psm[16w][128][8]fl2
// ---------------------------------------------------------------------------
#define SM_XP   0
#define SM_KSM  16384
#define SM_USM  (16384 + 4096)
#define SM_PSM  (16384 + 4096 + 512)
#define SM_ATT_FLOATS (SM_PSM + 16*128*16)   // 53760 floats = 215040 B
#define VT_STRIDE 20                          // vtile [512][20] overlays Psm

__global__ void __launch_bounds__(512, 1)
attn_kernel(const float* __restrict__ X,
            const float* __restrict__ ac,
            const float* __restrict__ alpha,
            const float* __restrict__ wkey,
            const float* __restrict__ u)
{
    extern __shared__ float sm[];
    float* Xp  = sm + SM_XP;
    float* Ksm = sm + SM_KSM;
    float* usm = sm + SM_USM;
    float* Psm = sm + SM_PSM;

    int bf   = blockIdx.x >> 4;
    int f    = bf & (NF - 1);
    int t0   = (blockIdx.x & 15) << 4;
    int tid  = threadIdx.x;
    int lane = tid & 31;
    int w    = tid >> 5;

    // ---- stage X (paired over l), K (per-head rows), u ----
    for (int i = tid; i < 128 * 64; i += 512) {
        int l2 = i >> 6, d = i & 63;
        const float* xr = X + (size_t)bf * (NT * DIN) + (size_t)(2 * l2) * DIN + d;
        float2 pr; pr.x = __ldg(xr); pr.y = __ldg(xr + DIN);
        *(float2*)&Xp[l2 * 128 + d * 2] = pr;
    }
    {
        const float* Kg = g_K + (size_t)bf * (NT * 16);
        for (int i = tid; i < NT * 16; i += 512) {
            float kv = Kg[i];
            int l = i >> 4, h = (i >> 1) & 7, e = i & 1;
            Ksm[h * 512 + l * 2 + e] = kv;
        }
        for (int i = tid; i < NT * 2; i += 512) usm[i] = __ldg(&u[f * (NT * 2) + i]);
    }
    __syncthreads();

    int t     = t0 + w;
    int idx_t = bf * NT + t;
    float alpha_f = __ldg(&alpha[f]);
    float a0 = __ldg(&wkey[f*4+0]), b0 = __ldg(&wkey[f*4+1]);
    float a1 = __ldg(&wkey[f*4+2]), b1 = __ldg(&wkey[f*4+3]);
    float v0 = -alpha_f;
    float* Pw = Psm + w * 2048;

    // ---- scores + softmax, two heads at a time; store P l-paired ----
#pragma unroll
    for (int hp = 0; hp < 4; hp++) {
        int h0 = hp * 2;
        float4 q4 = __ldg((const float4*)(g_Q + (size_t)idx_t * 16 + h0 * 2));
        float4 k4 = __ldg((const float4*)(g_K + (size_t)idx_t * 16 + h0 * 2));
        float v1a = 2.0f * alpha_f * __ldg(&ac[f * NH + h0]);
        float v1b = 2.0f * alpha_f * __ldg(&ac[f * NH + h0 + 1]);
        float qa0 = q4.x + v0, qa1 = q4.y + v1a;
        float A0 = fmaf(qa0, a0, qa1 * a1), B0 = fmaf(qa0, b0, qa1 * b1);
        float qb0 = q4.z + v0, qb1 = q4.w + v1b;
        float A1 = fmaf(qb0, a0, qb1 * a1), B1 = fmaf(qb0, b0, qb1 * b1);

        const float* Kh0 = Ksm + h0 * 512;
        const float* Kh1 = Kh0 + 512;
        float s0[8], s1[8], m0 = -3.4e38f, m1 = -3.4e38f;
#pragma unroll
        for (int j = 0; j < 8; j++) {
            int l = j * 32 + lane;
            float2 kv0 = *(const float2*)(Kh0 + l * 2);
            float2 kv1 = *(const float2*)(Kh1 + l * 2);
            float2 uv  = *(const float2*)(usm + l * 2);
            float r = (float)(l - t);
            float base0 = r * fmaf(A0, r, B0) + uv.x * k4.x + uv.y * k4.y;
            float base1 = r * fmaf(A1, r, B1) + uv.x * k4.z + uv.y * k4.w;
            base0 = fmaf(q4.x, kv0.x, base0); base0 = fmaf(q4.y, kv0.y, base0);
            base1 = fmaf(q4.z, kv1.x, base1); base1 = fmaf(q4.w, kv1.y, base1);
            s0[j] = base0; s1[j] = base1;
            m0 = fmaxf(m0, base0); m1 = fmaxf(m1, base1);
        }
#pragma unroll
        for (int o = 16; o; o >>= 1) {
            m0 = fmaxf(m0, __shfl_xor_sync(0xffffffffu, m0, o));
            m1 = fmaxf(m1, __shfl_xor_sync(0xffffffffu, m1, o));
        }
        float sum0 = 0.f, sum1 = 0.f;
#pragma unroll
        for (int j = 0; j < 8; j++) {
            s0[j] = __expf(s0[j] - m0); sum0 += s0[j];
            s1[j] = __expf(s1[j] - m1); sum1 += s1[j];
        }
#pragma unroll
        for (int o = 16; o; o >>= 1) {
            sum0 += __shfl_xor_sync(0xffffffffu, sum0, o);
            sum1 += __shfl_xor_sync(0xffffffffu, sum1, o);
        }
        float inv0 = 1.0f / sum0, inv1 = 1.0f / sum1;
#pragma unroll
        for (int j = 0; j < 8; j++) {
            float p0 = s0[j] * inv0, p1 = s1[j] * inv1;
            float p0o = __shfl_down_sync(0xffffffffu, p0, 1);
            float p1o = __shfl_down_sync(0xffffffffu, p1, 1);
            if (!(lane & 1)) {
                int l2 = j * 16 + (lane >> 1);
                float4 pk; pk.x = p0; pk.y = p0o; pk.z = p1; pk.w = p1o;
                *(float4*)&Pw[l2 * 16 + hp * 4] = pk;
            }
        }
    }
    __syncwarp();

    // ---- GEMM: vals[h][d] = sum_l P[l][h]*X[l][d], packed over l-pairs ----
    u64 acc[8][2];
#pragma unroll
    for (int h = 0; h < 8; h++) { acc[h][0] = 0ull; acc[h][1] = 0ull; }

    const float* XpL = Xp + lane * 4;
#pragma unroll 2
    for (int l2 = 0; l2 < 128; l2++) {
        ulonglong2 xv = *(const ulonglong2*)(XpL + l2 * 128);      // d=2lane, 2lane+1
        ulonglong2 pA = *(const ulonglong2*)(Pw + l2 * 16);        // h0,h1
        ulonglong2 pB = *(const ulonglong2*)(Pw + l2 * 16 + 4);    // h2,h3
        ulonglong2 pC = *(const ulonglong2*)(Pw + l2 * 16 + 8);
        ulonglong2 pD = *(const ulonglong2*)(Pw + l2 * 16 + 12);
        FFMA2(acc[0][0], pA.x, xv.x); FFMA2(acc[0][1], pA.x, xv.y);
        FFMA2(acc[1][0], pA.y, xv.x); FFMA2(acc[1][1], pA.y, xv.y);
        FFMA2(acc[2][0], pB.x, xv.x); FFMA2(acc[2][1], pB.x, xv.y);
        FFMA2(acc[3][0], pB.y, xv.x); FFMA2(acc[3][1], pB.y, xv.y);
        FFMA2(acc[4][0], pC.x, xv.x); FFMA2(acc[4][1], pC.x, xv.y);
        FFMA2(acc[5][0], pC.y, xv.x); FFMA2(acc[5][1], pC.y, xv.y);
        FFMA2(acc[6][0], pD.x, xv.x); FFMA2(acc[6][1], pD.x, xv.y);
        FFMA2(acc[7][0], pD.y, xv.x); FFMA2(acc[7][1], pD.y, xv.y);
    }

    float resA[8], resB[8];
#pragma unroll
    for (int h = 0; h < 8; h++) {
        resA[h] = lo32(acc[h][0]) + hi32(acc[h][0]);   // d = 2*lane
        resB[h] = lo32(acc[h][1]) + hi32(acc[h][1]);   // d = 2*lane+1
    }

    // ---- write vals transposed via smem vtile (overlays Psm) ----
    __syncthreads();
    float* vt = Psm;    // [512][VT_STRIDE], index [k][w]
#pragma unroll
    for (int h = 0; h < 8; h++) {
        int k = h * 64 + 2 * lane;
        vt[k * VT_STRIDE + w]       = resA[h];
        vt[(k + 1) * VT_STRIDE + w] = resB[h];
    }
    __syncthreads();

    float* gT = g_vals + (size_t)bf * (NK * NT) + t0;
    for (int i = tid; i < NK * 4; i += 512) {
        int k = i >> 2, q = i & 3;
        float4 vv = *(const float4*)(vt + k * VT_STRIDE + q * 4);
        *(float4*)(gT + (size_t)k * NT + q * 4) = vv;
    }
}

// ---------------------------------------------------------------------------
// Kernel 3: out[t][o] = valsT[:, t] . W[f][:, o] + b. FFMA2, W staged in smem.
// grid = BF*4 = 128 blocks (64 t each), 256 threads. Thread: 4t x 4o outputs.
// smem: VsT[512][68] + Wbuf[128*64]
// ---------------------------------------------------------------------------
#define VPAD 68
#define KCHUNK 128
#define SM3_VST 0
#define SM3_WB  (NK * VPAD)                       // 34816
#define SM3_FLOATS (SM3_WB + KCHUNK * DOUT)       // 43008 floats = 172032 B

__global__ void __launch_bounds__(256, 1)
out_kernel(const float* __restrict__ W,
           const float* __restrict__ Bv,
           float* __restrict__ Out)
{
    extern __shared__ float sm[];
    float* VsT  = sm + SM3_VST;
    float* Wbuf = sm + SM3_WB;

    int bf  = blockIdx.x >> 2;
    int f   = bf & (NF - 1);
    int t0  = (blockIdx.x & 3) << 6;
    int tid = threadIdx.x;

    // stage valsT rows (already [k][t] in global — straight coalesced copy)
    const float* gv = g_vals + (size_t)bf * (NK * NT) + t0;
    for (int i = tid; i < NK * 16; i += 256) {       // 512 k * 16 float4-per-row? (64 t = 16 f4)
        int k = i >> 4, tq = (i & 15) * 4;
        float4 v = __ldg((const float4*)(gv + (size_t)k * NT + tq));
        *(float4*)&VsT[k * VPAD + tq] = v;
    }
    __syncthreads();

    int oc = (tid & 15) * 4;
    int tg = tid >> 4;                                // [0,16): 4 t's each
    const float4* Wg4 = (const float4*)(W + (size_t)f * (NK * DOUT));

    u64 acc[4][2];
#pragma unroll
    for (int i = 0; i < 4; i++) { acc[i][0] = 0ull; acc[i][1] = 0ull; }

    for (int chunk = 0; chunk < NK / KCHUNK; chunk++) {
        for (int i = tid; i < KCHUNK * DOUT / 4; i += 256)
            ((float4*)Wbuf)[i] = __ldg(&Wg4[chunk * (KCHUNK * DOUT / 4) + i]);
        __syncthreads();

#pragma unroll 4
        for (int kk = 0; kk < KCHUNK; kk++) {
            int k = chunk * KCHUNK + kk;
            ulonglong2 w2 = *(const ulonglong2*)(Wbuf + kk * DOUT + oc);
            float4 v = *(const float4*)(VsT + k * VPAD + tg * 4);
            u64 d0, d1, d2, d3;
            DUP2(d0, v.x); DUP2(d1, v.y); DUP2(d2, v.z); DUP2(d3, v.w);
            FFMA2(acc[0][0], w2.x, d0); FFMA2(acc[0][1], w2.y, d0);
            FFMA2(acc[1][0], w2.x, d1); FFMA2(acc[1][1], w2.y, d1);
            FFMA2(acc[2][0], w2.x, d2); FFMA2(acc[2][1], w2.y, d2);
            FFMA2(acc[3][0], w2.x, d3); FFMA2(acc[3][1], w2.y, d3);
        }
        __syncthreads();
    }

#pragma unroll
    for (int i = 0; i < 4; i++) {
        int t = t0 + tg * 4 + i;
        float4 bb = __ldg((const float4*)(Bv + ((size_t)(f * NT + t)) * DOUT + oc));
        float4 r;
        r.x = lo32(acc[i][0]) + bb.x;
        r.y = hi32(acc[i][0]) + bb.y;
        r.z = lo32(acc[i][1]) + bb.z;
        r.w = hi32(acc[i][1]) + bb.w;
        *(float4*)(Out + ((size_t)(bf * NT + t)) * DOUT + oc) = r;
    }
}

// ---------------------------------------------------------------------------
extern "C" void kernel_launch(void* const* d_in, const int* in_sizes, int n_in,
                              void* d_out, int out_size)
{
    const float* X     = (const float*)d_in[0];
    const float* ac    = (const float*)d_in[1];
    const float* alpha = (const float*)d_in[2];
    const float* Wq    = (const float*)d_in[3];
    const float* Wk    = (const float*)d_in[4];
    const float* wkey  = (const float*)d_in[5];
    const float* u     = (const float*)d_in[6];
    const float* W     = (const float*)d_in[7];
    const float* Bv    = (const float*)d_in[8];
    float* Out = (float*)d_out;

    size_t smem2 = (size_t)SM_ATT_FLOATS * sizeof(float);  // 215040 B
    size_t smem3 = (size_t)SM3_FLOATS * sizeof(float);     // 172032 B
    cudaFuncSetAttribute(attn_kernel, cudaFuncAttributeMaxDynamicSharedMemorySize, (int)smem2);
    cudaFuncSetAttribute(out_kernel,  cudaFuncAttributeMaxDynamicSharedMemorySize, (int)smem3);

    qk_kernel<<<(BF * NT) / 8, 256>>>(X, Wq, Wk);
    attn_kernel<<<BF * 16, 512, smem2>>>(X, ac, alpha, wkey, u);
    out_kernel<<<BF * 4, 256, smem3>>>(W, Bv, Out);
}

// round 4
// speedup vs baseline: 2.2887x; 1.4042x over previous
#include <cuda_runtime.h>
#include <cstdint>
#include <cstddef>

#define BS 4
#define NF 8
#define NT 256
#define DIN 64
#define NH 8
#define DOUT 64
#define BF (BS*NF)          // 32
#define NK (NH*DIN)         // 512

// Scratch (allocation-free)
__device__ float g_Q[BF * NT * NH * 2];               // [bf][t][h][e]
__device__ float g_K[BF * NT * NH * 2];
__device__ float g_vals[(size_t)BF * NT * NK];        // [bf][t][k] fp32
__device__ unsigned g_Xt[(size_t)BF * DIN * NT];      // tf32 bits, [bf][d][l]
__device__ unsigned g_Wt[(size_t)NF * DOUT * NK];     // tf32 bits, [f][o][k]

static __device__ __forceinline__ unsigned f2tf32(float v) {
    unsigned t; asm("cvt.rna.tf32.f32 %0, %1;" : "=r"(t) : "f"(v)); return t;
}

// m16n8k8 row.col tf32 MMA (standard PTX, works on plain sm_103 target)
static __device__ __forceinline__ void mma8(float* d, unsigned a0, unsigned a1,
                                            unsigned a2, unsigned a3,
                                            unsigned b0, unsigned b1) {
    asm volatile("mma.sync.aligned.m16n8k8.row.col.f32.tf32.tf32.f32 "
        "{%0,%1,%2,%3}, {%4,%5,%6,%7}, {%8,%9}, {%0,%1,%2,%3};"
        : "+f"(d[0]), "+f"(d[1]), "+f"(d[2]), "+f"(d[3])
        : "r"(a0), "r"(a1), "r"(a2), "r"(a3), "r"(b0), "r"(b1));
}

// ---------------------------------------------------------------------------
// Prep: transpose X -> Xt[bf][d][l], W -> Wt[f][o][k] (tf32 bits).
// grid = 40 blocks (32 Xt + 8 Wt), 256 threads, smem 512*65*4 = 133120 B.
// ---------------------------------------------------------------------------
__global__ void prep_kernel(const float* __restrict__ X, const float* __restrict__ W)
{
    extern __shared__ float sm[];
    int tid = threadIdx.x;
    if (blockIdx.x < BF) {
        int bf = blockIdx.x;
        const float* Xg = X + (size_t)bf * NT * DIN;
        for (int i = tid; i < NT * DIN; i += 256) {
            int l = i >> 6, d = i & 63;
            sm[l * 65 + d] = __ldg(&Xg[i]);
        }
        __syncthreads();
        unsigned* out = g_Xt + (size_t)bf * DIN * NT;
        for (int i = tid; i < DIN * NT; i += 256) {
            int d = i >> 8, l = i & 255;
            out[i] = f2tf32(sm[l * 65 + d]);
        }
    } else {
        int f = blockIdx.x - BF;
        const float* Wg = W + (size_t)f * NK * DOUT;
        for (int i = tid; i < NK * DOUT; i += 256) {
            int k = i >> 6, o = i & 63;
            sm[k * 65 + o] = __ldg(&Wg[i]);
        }
        __syncthreads();
        unsigned* out = g_Wt + (size_t)f * DOUT * NK;
        for (int i = tid; i < DOUT * NK; i += 256) {
            int o = i >> 9, k = i & 511;
            out[i] = f2tf32(sm[k * 65 + o]);
        }
    }
}

// ---------------------------------------------------------------------------
// Kernel 1: Q/K projections (unchanged, works).
// ---------------------------------------------------------------------------
__global__ void qk_kernel(const float* __restrict__ X,
                          const float* __restrict__ Wq,
                          const float* __restrict__ Wk)
{
    int idx  = blockIdx.x * 8 + (threadIdx.x >> 5);
    int lane = threadIdx.x & 31;
    int t_ft = idx & (NF * NT - 1);

    const float* x = X + (size_t)idx * DIN;
    float x0 = __ldg(&x[lane]);
    float x1 = __ldg(&x[lane + 32]);

    int dq = lane >> 2;
    const float4* Wq4 = (const float4*)(Wq + (size_t)t_ft * (DIN * 16));
    const float4* Wk4 = (const float4*)(Wk + (size_t)t_ft * (DIN * 16));

    float4 aq = {0,0,0,0}, ak = {0,0,0,0};
#pragma unroll
    for (int i = 0; i < 8; i++) {
        int dsel = (i & 3) * 8 + dq;
        float xv = __shfl_sync(0xffffffffu, (i < 4) ? x0 : x1, dsel);
        float4 wq = __ldg(&Wq4[i * 32 + lane]);
        float4 wk = __ldg(&Wk4[i * 32 + lane]);
        aq.x = fmaf(xv, wq.x, aq.x); aq.y = fmaf(xv, wq.y, aq.y);
        aq.z = fmaf(xv, wq.z, aq.z); aq.w = fmaf(xv, wq.w, aq.w);
        ak.x = fmaf(xv, wk.x, ak.x); ak.y = fmaf(xv, wk.y, ak.y);
        ak.z = fmaf(xv, wk.z, ak.z); ak.w = fmaf(xv, wk.w, ak.w);
    }
#pragma unroll
    for (int off = 16; off >= 4; off >>= 1) {
        aq.x += __shfl_xor_sync(0xffffffffu, aq.x, off);
        aq.y += __shfl_xor_sync(0xffffffffu, aq.y, off);
        aq.z += __shfl_xor_sync(0xffffffffu, aq.z, off);
        aq.w += __shfl_xor_sync(0xffffffffu, aq.w, off);
        ak.x += __shfl_xor_sync(0xffffffffu, ak.x, off);
        ak.y += __shfl_xor_sync(0xffffffffu, ak.y, off);
        ak.z += __shfl_xor_sync(0xffffffffu, ak.z, off);
        ak.w += __shfl_xor_sync(0xffffffffu, ak.w, off);
    }
    if (lane < 4)      *(float4*)(g_Q + (size_t)idx * 16 + lane * 4) = aq;
    else if (lane < 8) *(float4*)(g_K + (size_t)idx * 16 + (lane - 4) * 4) = ak;
}

// ---------------------------------------------------------------------------
// Kernel 2: scores -> softmax -> P @ X^T via mma.sync (tf32).
// grid = BF*16 = 512, 512 threads. Stride 260 (≡4 mod 32) => conflict-free
// fragment loads (banks = 4*(lane/4) + lane%4, all distinct).
// smem words: P[128][260] | Xt[64][260] | Ksm 8*512 | usm 512  = 218112 B
// ---------------------------------------------------------------------------
#define SP 260
#define XT_OFF (128*SP)             // 33280
#define KS_OFF (XT_OFF + 64*SP)     // 49920
#define US_OFF (KS_OFF + 8*512)     // 54016
#define K2_BYTES ((US_OFF + 512)*4) // 218112

__global__ void __launch_bounds__(512, 1)
attn_kernel(const float* __restrict__ ac,
            const float* __restrict__ alpha,
            const float* __restrict__ wkey,
            const float* __restrict__ u)
{
    extern __shared__ float sm[];
    unsigned* Pb  = (unsigned*)sm;            // [128][SP] tf32 bits
    unsigned* Xtb = (unsigned*)sm + XT_OFF;   // [64][SP]
    float* Ksm = sm + KS_OFF;
    float* usm = sm + US_OFF;

    int bf   = blockIdx.x >> 4;
    int f    = bf & (NF - 1);
    int t0   = (blockIdx.x & 15) << 4;
    int tid  = threadIdx.x;
    int lane = tid & 31;
    int w    = tid >> 5;

    // ---- stage Xt (tf32 bits, coalesced, conflict-free) ----
    const unsigned* Xg = g_Xt + (size_t)bf * DIN * NT;
    for (int i = tid; i < DIN * NT; i += 512) {
        int d = i >> 8, l = i & 255;
        Xtb[d * SP + l] = __ldg(&Xg[i]);
    }
    // ---- stage K (per-head rows), u ----
    {
        const float* Kg = g_K + (size_t)bf * (NT * 16);
        for (int i = tid; i < NT * 16; i += 512) {
            float kv = Kg[i];
            int l = i >> 4, h = (i >> 1) & 7, e = i & 1;
            Ksm[h * 512 + l * 2 + e] = kv;
        }
        for (int i = tid; i < NT * 2; i += 512) usm[i] = __ldg(&u[f * (NT * 2) + i]);
    }
    __syncthreads();

    int t     = t0 + w;
    int idx_t = bf * NT + t;
    float alpha_f = __ldg(&alpha[f]);
    float a0c = __ldg(&wkey[f*4+0]), b0c = __ldg(&wkey[f*4+1]);
    float a1c = __ldg(&wkey[f*4+2]), b1c = __ldg(&wkey[f*4+3]);
    float v0 = -alpha_f;

    // ---- scores + softmax; P row = 8*w + h, tf32 bits ----
#pragma unroll
    for (int hp = 0; hp < 4; hp++) {
        int h0 = hp * 2;
        float4 q4 = __ldg((const float4*)(g_Q + (size_t)idx_t * 16 + h0 * 2));
        float4 k4 = __ldg((const float4*)(g_K + (size_t)idx_t * 16 + h0 * 2));
        float v1a = 2.0f * alpha_f * __ldg(&ac[f * NH + h0]);
        float v1b = 2.0f * alpha_f * __ldg(&ac[f * NH + h0 + 1]);
        float qa0 = q4.x + v0, qa1 = q4.y + v1a;
        float A0 = fmaf(qa0, a0c, qa1 * a1c), B0 = fmaf(qa0, b0c, qa1 * b1c);
        float qb0 = q4.z + v0, qb1 = q4.w + v1b;
        float A1 = fmaf(qb0, a0c, qb1 * a1c), B1 = fmaf(qb0, b0c, qb1 * b1c);

        const float* Kh0 = Ksm + h0 * 512;
        const float* Kh1 = Kh0 + 512;
        float s0[8], s1[8], m0 = -3.4e38f, m1 = -3.4e38f;
#pragma unroll
        for (int j = 0; j < 8; j++) {
            int l = j * 32 + lane;
            float2 kv0 = *(const float2*)(Kh0 + l * 2);
            float2 kv1 = *(const float2*)(Kh1 + l * 2);
            float2 uv  = *(const float2*)(usm + l * 2);
            float r = (float)(l - t);
            float base0 = r * fmaf(A0, r, B0) + uv.x * k4.x + uv.y * k4.y;
            float base1 = r * fmaf(A1, r, B1) + uv.x * k4.z + uv.y * k4.w;
            base0 = fmaf(q4.x, kv0.x, base0); base0 = fmaf(q4.y, kv0.y, base0);
            base1 = fmaf(q4.z, kv1.x, base1); base1 = fmaf(q4.w, kv1.y, base1);
            s0[j] = base0; s1[j] = base1;
            m0 = fmaxf(m0, base0); m1 = fmaxf(m1, base1);
        }
#pragma unroll
        for (int o = 16; o; o >>= 1) {
            m0 = fmaxf(m0, __shfl_xor_sync(0xffffffffu, m0, o));
            m1 = fmaxf(m1, __shfl_xor_sync(0xffffffffu, m1, o));
        }
        float sum0 = 0.f, sum1 = 0.f;
#pragma unroll
        for (int j = 0; j < 8; j++) {
            s0[j] = __expf(s0[j] - m0); sum0 += s0[j];
            s1[j] = __expf(s1[j] - m1); sum1 += s1[j];
        }
#pragma unroll
        for (int o = 16; o; o >>= 1) {
            sum0 += __shfl_xor_sync(0xffffffffu, sum0, o);
            sum1 += __shfl_xor_sync(0xffffffffu, sum1, o);
        }
        float inv0 = 1.0f / sum0, inv1 = 1.0f / sum1;
        unsigned* pr0 = Pb + (8 * w + h0) * SP;
#pragma unroll
        for (int j = 0; j < 8; j++) {
            int l = j * 32 + lane;
            pr0[l]      = f2tf32(s0[j] * inv0);
            pr0[SP + l] = f2tf32(s1[j] * inv1);
        }
    }
    __syncthreads();

    // ---- block MMA: D[th=128][d=64] = P @ Xt^T, K = 256 ----
    int g  = lane >> 2;
    int s4 = lane & 3;
    int mi = w & 7;
    int n0 = (w >> 3) * 32;

    const unsigned* aP = Pb + (16 * mi + g) * SP + s4;
    float acc[4][4];
#pragma unroll
    for (int i = 0; i < 4; i++)
#pragma unroll
        for (int j = 0; j < 4; j++) acc[i][j] = 0.f;

#pragma unroll 4
    for (int k0 = 0; k0 < 256; k0 += 8) {
        unsigned a0 = aP[k0];
        unsigned a1 = aP[k0 + 8 * SP];
        unsigned a2 = aP[k0 + 4];
        unsigned a3 = aP[k0 + 8 * SP + 4];
#pragma unroll
        for (int nt = 0; nt < 4; nt++) {
            const unsigned* bB = Xtb + (n0 + 8 * nt + g) * SP + s4 + k0;
            mma8(acc[nt], a0, a1, a2, a3, bB[0], bB[4]);
        }
    }

    // ---- epilogue: write vals[bf][t][h*64+d] fp32 ----
    int thA = 16 * mi + g, thB = thA + 8;
    float* rowA = g_vals + ((size_t)(bf * NT + t0 + (thA >> 3))) * NK + (thA & 7) * 64;
    float* rowB = g_vals + ((size_t)(bf * NT + t0 + (thB >> 3))) * NK + (thB & 7) * 64;
#pragma unroll
    for (int nt = 0; nt < 4; nt++) {
        int d = n0 + 8 * nt + 2 * s4;
        *(float2*)(rowA + d) = make_float2(acc[nt][0], acc[nt][1]);
        *(float2*)(rowB + d) = make_float2(acc[nt][2], acc[nt][3]);
    }
}

// ---------------------------------------------------------------------------
// Kernel 3: out[t][o] = vals @ W + b via mma.sync tf32.
// grid = BF*4 = 128 blocks (64 t each), 256 threads (8 warps).
// smem: A[64][260] + B[64][260] tf32 bits = 133120 B; K staged in 2 chunks.
// ---------------------------------------------------------------------------
#define SA 260
#define K3_BYTES (2 * 64 * SA * 4)   // 133120

__global__ void __launch_bounds__(256, 1)
out_kernel(const float* __restrict__ Bv, float* __restrict__ Out)
{
    extern __shared__ float sm[];
    unsigned* Ab = (unsigned*)sm;             // vals tf32 [64][SA]
    unsigned* Bb = (unsigned*)sm + 64 * SA;   // Wt tf32  [64][SA]

    int bf  = blockIdx.x >> 2;
    int f   = bf & (NF - 1);
    int t0  = (blockIdx.x & 3) << 6;
    int tid = threadIdx.x;
    int lane = tid & 31;
    int w   = tid >> 5;

    int g  = lane >> 2;
    int s4 = lane & 3;
    int mi = w & 3;
    int n0 = (w >> 2) * 32;

    float acc[4][4];
#pragma unroll
    for (int i = 0; i < 4; i++)
#pragma unroll
        for (int j = 0; j < 4; j++) acc[i][j] = 0.f;

    for (int kc = 0; kc < 2; kc++) {
        const float* gv = g_vals + ((size_t)(bf * NT + t0)) * NK + kc * 256;
        for (int i = tid; i < 64 * 256; i += 256) {
            int m = i >> 8, kk = i & 255;
            Ab[m * SA + kk] = f2tf32(__ldg(&gv[(size_t)m * NK + kk]));
        }
        const unsigned* gw = g_Wt + (size_t)f * DOUT * NK + kc * 256;
        for (int i = tid; i < 64 * 256; i += 256) {
            int o = i >> 8, kk = i & 255;
            Bb[o * SA + kk] = __ldg(&gw[(size_t)o * NK + kk]);
        }
        __syncthreads();

        const unsigned* aP = Ab + (16 * mi + g) * SA + s4;
#pragma unroll 4
        for (int k0 = 0; k0 < 256; k0 += 8) {
            unsigned a0 = aP[k0];
            unsigned a1 = aP[k0 + 8 * SA];
            unsigned a2 = aP[k0 + 4];
            unsigned a3 = aP[k0 + 8 * SA + 4];
#pragma unroll
            for (int nt = 0; nt < 4; nt++) {
                const unsigned* bB = Bb + (n0 + 8 * nt + g) * SA + s4 + k0;
                mma8(acc[nt], a0, a1, a2, a3, bB[0], bB[4]);
            }
        }
        __syncthreads();
    }

    // epilogue: rows tA = t0+16mi+g, tB = +8; cols o = n0+8nt+2s4
    int tA = t0 + 16 * mi + g, tB = tA + 8;
    const float* bvA = Bv + ((size_t)(f * NT + tA)) * DOUT;
    const float* bvB = Bv + ((size_t)(f * NT + tB)) * DOUT;
    float* oA = Out + ((size_t)(bf * NT + tA)) * DOUT;
    float* oB = Out + ((size_t)(bf * NT + tB)) * DOUT;
#pragma unroll
    for (int nt = 0; nt < 4; nt++) {
        int o = n0 + 8 * nt + 2 * s4;
        float2 ba = __ldg((const float2*)(bvA + o));
        float2 bb = __ldg((const float2*)(bvB + o));
        *(float2*)(oA + o) = make_float2(acc[nt][0] + ba.x, acc[nt][1] + ba.y);
        *(float2*)(oB + o) = make_float2(acc[nt][2] + bb.x, acc[nt][3] + bb.y);
    }
}

// ---------------------------------------------------------------------------
extern "C" void kernel_launch(void* const* d_in, const int* in_sizes, int n_in,
                              void* d_out, int out_size)
{
    const float* X     = (const float*)d_in[0];
    const float* ac    = (const float*)d_in[1];
    const float* alpha = (const float*)d_in[2];
    const float* Wq    = (const float*)d_in[3];
    const float* Wk    = (const float*)d_in[4];
    const float* wkey  = (const float*)d_in[5];
    const float* u     = (const float*)d_in[6];
    const float* W     = (const float*)d_in[7];
    const float* Bv    = (const float*)d_in[8];
    float* Out = (float*)d_out;

    cudaFuncSetAttribute(prep_kernel, cudaFuncAttributeMaxDynamicSharedMemorySize, 133120);
    cudaFuncSetAttribute(attn_kernel, cudaFuncAttributeMaxDynamicSharedMemorySize, K2_BYTES);
    cudaFuncSetAttribute(out_kernel,  cudaFuncAttributeMaxDynamicSharedMemorySize, K3_BYTES);

    prep_kernel<<<40, 256, 133120>>>(X, W);
    qk_kernel<<<(BF * NT) / 8, 256>>>(X, Wq, Wk);
    attn_kernel<<<BF * 16, 512, K2_BYTES>>>(ac, alpha, wkey, u);
    out_kernel<<<BF * 4, 256, K3_BYTES>>>(Bv, Out);
}

// round 5
// speedup vs baseline: 2.4393x; 1.0658x over previous
#include <cuda_runtime.h>
#include <cstdint>
#include <cstddef>

#define BS 4
#define NF 8
#define NT 256
#define DIN 64
#define NH 8
#define DOUT 64
#define BF (BS*NF)          // 32
#define NK (NH*DIN)         // 512

// Scratch (allocation-free)
__device__ float g_Q[BF * NT * NH * 2];               // [bf][t][h][e]
__device__ float g_K[BF * NT * NH * 2];
__device__ unsigned g_Xt[(size_t)BF * DIN * NT];      // tf32 bits, [bf][d][l]
__device__ unsigned g_Wt[(size_t)NF * DOUT * NK];     // tf32 bits, [f][o][k]

static __device__ __forceinline__ unsigned f2tf32(float v) {
    unsigned t; asm("cvt.rna.tf32.f32 %0, %1;" : "=r"(t) : "f"(v)); return t;
}

// m16n8k8 row.col tf32 MMA (standard PTX, works on plain sm_103 target)
static __device__ __forceinline__ void mma8(float* d, unsigned a0, unsigned a1,
                                            unsigned a2, unsigned a3,
                                            unsigned b0, unsigned b1) {
    asm volatile("mma.sync.aligned.m16n8k8.row.col.f32.tf32.tf32.f32 "
        "{%0,%1,%2,%3}, {%4,%5,%6,%7}, {%8,%9}, {%0,%1,%2,%3};"
        : "+f"(d[0]), "+f"(d[1]), "+f"(d[2]), "+f"(d[3])
        : "r"(a0), "r"(a1), "r"(a2), "r"(a3), "r"(b0), "r"(b1));
}

// ---------------------------------------------------------------------------
// Prep: transpose X -> Xt[bf][d][l], W -> Wt[f][o][k] (tf32 bits).
// grid = 40 blocks (32 Xt + 8 Wt), 256 threads, smem 512*65*4 = 133120 B.
// ---------------------------------------------------------------------------
__global__ void prep_kernel(const float* __restrict__ X, const float* __restrict__ W)
{
    extern __shared__ float sm[];
    int tid = threadIdx.x;
    if (blockIdx.x < BF) {
        int bf = blockIdx.x;
        const float* Xg = X + (size_t)bf * NT * DIN;
        for (int i = tid; i < NT * DIN; i += 256) {
            int l = i >> 6, d = i & 63;
            sm[l * 65 + d] = __ldg(&Xg[i]);
        }
        __syncthreads();
        unsigned* out = g_Xt + (size_t)bf * DIN * NT;
        for (int i = tid; i < DIN * NT; i += 256) {
            int d = i >> 8, l = i & 255;
            out[i] = f2tf32(sm[l * 65 + d]);
        }
    } else {
        int f = blockIdx.x - BF;
        const float* Wg = W + (size_t)f * NK * DOUT;
        for (int i = tid; i < NK * DOUT; i += 256) {
            int k = i >> 6, o = i & 63;
            sm[k * 65 + o] = __ldg(&Wg[i]);
        }
        __syncthreads();
        unsigned* out = g_Wt + (size_t)f * DOUT * NK;
        for (int i = tid; i < DOUT * NK; i += 256) {
            int o = i >> 9, k = i & 511;
            out[i] = f2tf32(sm[k * 65 + o]);
        }
    }
}

// ---------------------------------------------------------------------------
// Kernel 1: Q/K projections (unchanged, works).
// ---------------------------------------------------------------------------
__global__ void qk_kernel(const float* __restrict__ X,
                          const float* __restrict__ Wq,
                          const float* __restrict__ Wk)
{
    int idx  = blockIdx.x * 8 + (threadIdx.x >> 5);
    int lane = threadIdx.x & 31;
    int t_ft = idx & (NF * NT - 1);

    const float* x = X + (size_t)idx * DIN;
    float x0 = __ldg(&x[lane]);
    float x1 = __ldg(&x[lane + 32]);

    int dq = lane >> 2;
    const float4* Wq4 = (const float4*)(Wq + (size_t)t_ft * (DIN * 16));
    const float4* Wk4 = (const float4*)(Wk + (size_t)t_ft * (DIN * 16));

    float4 aq = {0,0,0,0}, ak = {0,0,0,0};
#pragma unroll
    for (int i = 0; i < 8; i++) {
        int dsel = (i & 3) * 8 + dq;
        float xv = __shfl_sync(0xffffffffu, (i < 4) ? x0 : x1, dsel);
        float4 wq = __ldg(&Wq4[i * 32 + lane]);
        float4 wk = __ldg(&Wk4[i * 32 + lane]);
        aq.x = fmaf(xv, wq.x, aq.x); aq.y = fmaf(xv, wq.y, aq.y);
        aq.z = fmaf(xv, wq.z, aq.z); aq.w = fmaf(xv, wq.w, aq.w);
        ak.x = fmaf(xv, wk.x, ak.x); ak.y = fmaf(xv, wk.y, ak.y);
        ak.z = fmaf(xv, wk.z, ak.z); ak.w = fmaf(xv, wk.w, ak.w);
    }
#pragma unroll
    for (int off = 16; off >= 4; off >>= 1) {
        aq.x += __shfl_xor_sync(0xffffffffu, aq.x, off);
        aq.y += __shfl_xor_sync(0xffffffffu, aq.y, off);
        aq.z += __shfl_xor_sync(0xffffffffu, aq.z, off);
        aq.w += __shfl_xor_sync(0xffffffffu, aq.w, off);
        ak.x += __shfl_xor_sync(0xffffffffu, ak.x, off);
        ak.y += __shfl_xor_sync(0xffffffffu, ak.y, off);
        ak.z += __shfl_xor_sync(0xffffffffu, ak.z, off);
        ak.w += __shfl_xor_sync(0xffffffffu, ak.w, off);
    }
    if (lane < 4)      *(float4*)(g_Q + (size_t)idx * 16 + lane * 4) = aq;
    else if (lane < 8) *(float4*)(g_K + (size_t)idx * 16 + (lane - 4) * 4) = ak;
}

// ---------------------------------------------------------------------------
// Kernel 2 (FUSED): scores -> softmax -> P@X^T -> vals@W + b -> Out.
// grid = BF*16 = 512, 512 threads.
// Phase A smem: P[128][260] | Xt[64][260] | Ksm 8*512 | usm 512  (218112 B)
// Phase B smem (overlaid): Bw[64][516] over P | Av[16][516] over Xt |
//                          red[1024] over Ksm
// ---------------------------------------------------------------------------
#define SP 260
#define SBW 516
#define SAV 516
#define XT_OFF (128*SP)             // 33280
#define KS_OFF (XT_OFF + 64*SP)     // 49920
#define US_OFF (KS_OFF + 8*512)     // 54016
#define K2_BYTES ((US_OFF + 512)*4) // 218112

__global__ void __launch_bounds__(512, 1)
attn_kernel(const float* __restrict__ ac,
            const float* __restrict__ alpha,
            const float* __restrict__ wkey,
            const float* __restrict__ u,
            const float* __restrict__ Bv,
            float* __restrict__ Out)
{
    extern __shared__ float sm[];
    unsigned* Pb  = (unsigned*)sm;            // [128][SP] tf32 bits
    unsigned* Xtb = (unsigned*)sm + XT_OFF;   // [64][SP]
    float* Ksm = sm + KS_OFF;
    float* usm = sm + US_OFF;
    // phase-B overlays
    unsigned* Bw  = (unsigned*)sm;            // [64][SBW]
    unsigned* Av  = (unsigned*)sm + XT_OFF;   // [16][SAV]
    float* red = sm + KS_OFF;                 // [8][32][4]

    int bf   = blockIdx.x >> 4;
    int f    = bf & (NF - 1);
    int t0   = (blockIdx.x & 15) << 4;
    int tid  = threadIdx.x;
    int lane = tid & 31;
    int w    = tid >> 5;

    // ---- stage Xt (tf32 bits), K rows, u ----
    const unsigned* Xg = g_Xt + (size_t)bf * DIN * NT;
    for (int i = tid; i < DIN * NT; i += 512) {
        int d = i >> 8, l = i & 255;
        Xtb[d * SP + l] = __ldg(&Xg[i]);
    }
    {
        const float* Kg = g_K + (size_t)bf * (NT * 16);
        for (int i = tid; i < NT * 16; i += 512) {
            float kv = Kg[i];
            int l = i >> 4, h = (i >> 1) & 7, e = i & 1;
            Ksm[h * 512 + l * 2 + e] = kv;
        }
        for (int i = tid; i < NT * 2; i += 512) usm[i] = __ldg(&u[f * (NT * 2) + i]);
    }
    __syncthreads();

    int t     = t0 + w;
    int idx_t = bf * NT + t;
    float alpha_f = __ldg(&alpha[f]);
    float a0c = __ldg(&wkey[f*4+0]), b0c = __ldg(&wkey[f*4+1]);
    float a1c = __ldg(&wkey[f*4+2]), b1c = __ldg(&wkey[f*4+3]);
    float v0 = -alpha_f;

    // ---- scores + softmax; P row = 8*w + h, tf32 bits ----
#pragma unroll
    for (int hp = 0; hp < 4; hp++) {
        int h0 = hp * 2;
        float4 q4 = __ldg((const float4*)(g_Q + (size_t)idx_t * 16 + h0 * 2));
        float4 k4 = __ldg((const float4*)(g_K + (size_t)idx_t * 16 + h0 * 2));
        float v1a = 2.0f * alpha_f * __ldg(&ac[f * NH + h0]);
        float v1b = 2.0f * alpha_f * __ldg(&ac[f * NH + h0 + 1]);
        float qa0 = q4.x + v0, qa1 = q4.y + v1a;
        float A0 = fmaf(qa0, a0c, qa1 * a1c), B0 = fmaf(qa0, b0c, qa1 * b1c);
        float qb0 = q4.z + v0, qb1 = q4.w + v1b;
        float A1 = fmaf(qb0, a0c, qb1 * a1c), B1 = fmaf(qb0, b0c, qb1 * b1c);

        const float* Kh0 = Ksm + h0 * 512;
        const float* Kh1 = Kh0 + 512;
        float s0[8], s1[8], m0 = -3.4e38f, m1 = -3.4e38f;
#pragma unroll
        for (int j = 0; j < 8; j++) {
            int l = j * 32 + lane;
            float2 kv0 = *(const float2*)(Kh0 + l * 2);
            float2 kv1 = *(const float2*)(Kh1 + l * 2);
            float2 uv  = *(const float2*)(usm + l * 2);
            float r = (float)(l - t);
            float base0 = r * fmaf(A0, r, B0) + uv.x * k4.x + uv.y * k4.y;
            float base1 = r * fmaf(A1, r, B1) + uv.x * k4.z + uv.y * k4.w;
            base0 = fmaf(q4.x, kv0.x, base0); base0 = fmaf(q4.y, kv0.y, base0);
            base1 = fmaf(q4.z, kv1.x, base1); base1 = fmaf(q4.w, kv1.y, base1);
            s0[j] = base0; s1[j] = base1;
            m0 = fmaxf(m0, base0); m1 = fmaxf(m1, base1);
        }
#pragma unroll
        for (int o = 16; o; o >>= 1) {
            m0 = fmaxf(m0, __shfl_xor_sync(0xffffffffu, m0, o));
            m1 = fmaxf(m1, __shfl_xor_sync(0xffffffffu, m1, o));
        }
        float sum0 = 0.f, sum1 = 0.f;
#pragma unroll
        for (int j = 0; j < 8; j++) {
            s0[j] = __expf(s0[j] - m0); sum0 += s0[j];
            s1[j] = __expf(s1[j] - m1); sum1 += s1[j];
        }
#pragma unroll
        for (int o = 16; o; o >>= 1) {
            sum0 += __shfl_xor_sync(0xffffffffu, sum0, o);
            sum1 += __shfl_xor_sync(0xffffffffu, sum1, o);
        }
        float inv0 = 1.0f / sum0, inv1 = 1.0f / sum1;
        unsigned* pr0 = Pb + (8 * w + h0) * SP;
#pragma unroll
        for (int j = 0; j < 8; j++) {
            int l = j * 32 + lane;
            pr0[l]      = f2tf32(s0[j] * inv0);
            pr0[SP + l] = f2tf32(s1[j] * inv1);
        }
    }
    __syncthreads();

    // ---- MMA1: D[th=128][d=64] = P @ Xt^T, K = 256 ----
    int g  = lane >> 2;
    int s4 = lane & 3;
    int mi = w & 7;
    int n0 = (w >> 3) * 32;

    const unsigned* aP = Pb + (16 * mi + g) * SP + s4;
    float acc[4][4];
#pragma unroll
    for (int i = 0; i < 4; i++)
#pragma unroll
        for (int j = 0; j < 4; j++) acc[i][j] = 0.f;

#pragma unroll 4
    for (int k0 = 0; k0 < 256; k0 += 8) {
        unsigned a0 = aP[k0];
        unsigned a1 = aP[k0 + 8 * SP];
        unsigned a2 = aP[k0 + 4];
        unsigned a3 = aP[k0 + 8 * SP + 4];
#pragma unroll
        for (int nt = 0; nt < 4; nt++) {
            const unsigned* bB = Xtb + (n0 + 8 * nt + g) * SP + s4 + k0;
            mma8(acc[nt], a0, a1, a2, a3, bB[0], bB[4]);
        }
    }
    __syncthreads();   // P and Xt now dead; overlays become writable

    // ---- phase B staging: Bw = W[f] tf32 (from g_Wt), Av = vals tf32 ----
    {
        const uint4* gw = (const uint4*)(g_Wt + (size_t)f * DOUT * NK);
        for (int i = tid; i < DOUT * NK / 4; i += 512) {
            int o = i >> 7, k4i = (i & 127) * 4;
            uint4 v = __ldg(&gw[i]);
            *(uint4*)&Bw[o * SBW + k4i] = v;
        }
    }
    {
        int thA = 16 * mi + g, thB = thA + 8;
        int tA = thA >> 3, hA = thA & 7;
        int tB = thB >> 3, hB = thB & 7;
#pragma unroll
        for (int nt = 0; nt < 4; nt++) {
            int d = n0 + 8 * nt + 2 * s4;
            uint2 pa, pb;
            pa.x = f2tf32(acc[nt][0]); pa.y = f2tf32(acc[nt][1]);
            pb.x = f2tf32(acc[nt][2]); pb.y = f2tf32(acc[nt][3]);
            *(uint2*)&Av[tA * SAV + hA * 64 + d] = pa;
            *(uint2*)&Av[tB * SAV + hB * 64 + d] = pb;
        }
    }
    __syncthreads();

    // ---- MMA2: Out[16 t][64 o] = Av @ Bw^T + b.  16 warps: n-split 8, k-split 2.
    int ni = w & 7;
    int kh = w >> 3;
    int n0b = ni * 8;
    int kk0 = kh * 256;

    float acc2[4] = {0.f, 0.f, 0.f, 0.f};
    const unsigned* aP2 = Av + g * SAV + s4 + kk0;
    const unsigned* bP2 = Bw + (n0b + g) * SBW + s4 + kk0;
#pragma unroll 8
    for (int k0 = 0; k0 < 256; k0 += 8) {
        unsigned a0 = aP2[k0];
        unsigned a1 = aP2[k0 + 8 * SAV];
        unsigned a2 = aP2[k0 + 4];
        unsigned a3 = aP2[k0 + 8 * SAV + 4];
        mma8(acc2, a0, a1, a2, a3, bP2[k0], bP2[k0 + 4]);
    }
    __syncthreads();   // Ksm region dead -> red
    if (kh == 1) {
        float* r = red + (ni * 32 + lane) * 4;
        r[0] = acc2[0]; r[1] = acc2[1]; r[2] = acc2[2]; r[3] = acc2[3];
    }
    __syncthreads();
    if (kh == 0) {
        const float* r = red + (ni * 32 + lane) * 4;
        acc2[0] += r[0]; acc2[1] += r[1]; acc2[2] += r[2]; acc2[3] += r[3];

        int tA = t0 + g, tB = tA + 8;
        int oc = n0b + 2 * s4;
        float2 ba = __ldg((const float2*)(Bv + ((size_t)(f * NT + tA)) * DOUT + oc));
        float2 bb = __ldg((const float2*)(Bv + ((size_t)(f * NT + tB)) * DOUT + oc));
        *(float2*)(Out + ((size_t)(bf * NT + tA)) * DOUT + oc) =
            make_float2(acc2[0] + ba.x, acc2[1] + ba.y);
        *(float2*)(Out + ((size_t)(bf * NT + tB)) * DOUT + oc) =
            make_float2(acc2[2] + bb.x, acc2[3] + bb.y);
    }
}

// ---------------------------------------------------------------------------
extern "C" void kernel_launch(void* const* d_in, const int* in_sizes, int n_in,
                              void* d_out, int out_size)
{
    const float* X     = (const float*)d_in[0];
    const float* ac    = (const float*)d_in[1];
    const float* alpha = (const float*)d_in[2];
    const float* Wq    = (const float*)d_in[3];
    const float* Wk    = (const float*)d_in[4];
    const float* wkey  = (const float*)d_in[5];
    const float* u     = (const float*)d_in[6];
    const float* W     = (const float*)d_in[7];
    const float* Bv    = (const float*)d_in[8];
    float* Out = (float*)d_out;

    cudaFuncSetAttribute(prep_kernel, cudaFuncAttributeMaxDynamicSharedMemorySize, 133120);
    cudaFuncSetAttribute(attn_kernel, cudaFuncAttributeMaxDynamicSharedMemorySize, K2_BYTES);

    prep_kernel<<<40, 256, 133120>>>(X, W);
    qk_kernel<<<(BF * NT) / 8, 256>>>(X, Wq, Wk);
    attn_kernel<<<BF * 16, 512, K2_BYTES>>>(ac, alpha, wkey, u, Bv, Out);
}

// round 6
// speedup vs baseline: 2.5616x; 1.0501x over previous
#include <cuda_runtime.h>
#include <cstdint>
#include <cstddef>

#define BS 4
#define NF 8
#define NT 256
#define DIN 64
#define NH 8
#define DOUT 64
#define BF (BS*NF)          // 32
#define NK (NH*DIN)         // 512

// Scratch (allocation-free)
__device__ float g_Q[BF * NT * NH * 2];               // [bf][t][h][e]
__device__ float g_K[BF * NT * NH * 2];
__device__ unsigned g_Xt[(size_t)BF * DIN * NT];      // tf32 bits, [bf][d][l]
__device__ unsigned g_Wt[(size_t)NF * DOUT * NK];     // tf32 bits, [f][o][k]

static __device__ __forceinline__ unsigned f2tf32(float v) {
    unsigned t; asm("cvt.rna.tf32.f32 %0, %1;" : "=r"(t) : "f"(v)); return t;
}

static __device__ __forceinline__ void mma8(float* d, unsigned a0, unsigned a1,
                                            unsigned a2, unsigned a3,
                                            unsigned b0, unsigned b1) {
    asm volatile("mma.sync.aligned.m16n8k8.row.col.f32.tf32.tf32.f32 "
        "{%0,%1,%2,%3}, {%4,%5,%6,%7}, {%8,%9}, {%0,%1,%2,%3};"
        : "+f"(d[0]), "+f"(d[1]), "+f"(d[2]), "+f"(d[3])
        : "r"(a0), "r"(a1), "r"(a2), "r"(a3), "r"(b0), "r"(b1));
}

// ---------------------------------------------------------------------------
// Fused pre-kernel: blocks [0,1024) = QK projections; [1024,1152) = X->Xt
// 64x64 tile transposes; [1152,1216) = W->Wt tile transposes.
// 256 threads, 16640 B dynamic smem (transpose tiles only).
// ---------------------------------------------------------------------------
#define QK_BLOCKS 1024
#define XT_BLOCKS 128
#define WT_BLOCKS 64

__global__ void __launch_bounds__(256)
pre_kernel(const float* __restrict__ X,
           const float* __restrict__ Wq,
           const float* __restrict__ Wk,
           const float* __restrict__ W)
{
    extern __shared__ float tsm[];   // [64][65]
    int tid = threadIdx.x;

    if (blockIdx.x < QK_BLOCKS) {
        // ---- QK projection: warp per (b,f,t) ----
        int idx  = blockIdx.x * 8 + (tid >> 5);
        int lane = tid & 31;
        int t_ft = idx & (NF * NT - 1);

        const float* x = X + (size_t)idx * DIN;
        float x0 = __ldg(&x[lane]);
        float x1 = __ldg(&x[lane + 32]);

        int dq = lane >> 2;
        const float4* Wq4 = (const float4*)(Wq + (size_t)t_ft * (DIN * 16));
        const float4* Wk4 = (const float4*)(Wk + (size_t)t_ft * (DIN * 16));

        // batch all 16 loads for MLP
        float4 wq[8], wk[8];
#pragma unroll
        for (int i = 0; i < 8; i++) {
            wq[i] = __ldg(&Wq4[i * 32 + lane]);
            wk[i] = __ldg(&Wk4[i * 32 + lane]);
        }

        float4 aq = {0,0,0,0}, ak = {0,0,0,0};
#pragma unroll
        for (int i = 0; i < 8; i++) {
            int dsel = (i & 3) * 8 + dq;
            float xv = __shfl_sync(0xffffffffu, (i < 4) ? x0 : x1, dsel);
            aq.x = fmaf(xv, wq[i].x, aq.x); aq.y = fmaf(xv, wq[i].y, aq.y);
            aq.z = fmaf(xv, wq[i].z, aq.z); aq.w = fmaf(xv, wq[i].w, aq.w);
            ak.x = fmaf(xv, wk[i].x, ak.x); ak.y = fmaf(xv, wk[i].y, ak.y);
            ak.z = fmaf(xv, wk[i].z, ak.z); ak.w = fmaf(xv, wk[i].w, ak.w);
        }
#pragma unroll
        for (int off = 16; off >= 4; off >>= 1) {
            aq.x += __shfl_xor_sync(0xffffffffu, aq.x, off);
            aq.y += __shfl_xor_sync(0xffffffffu, aq.y, off);
            aq.z += __shfl_xor_sync(0xffffffffu, aq.z, off);
            aq.w += __shfl_xor_sync(0xffffffffu, aq.w, off);
            ak.x += __shfl_xor_sync(0xffffffffu, ak.x, off);
            ak.y += __shfl_xor_sync(0xffffffffu, ak.y, off);
            ak.z += __shfl_xor_sync(0xffffffffu, ak.z, off);
            ak.w += __shfl_xor_sync(0xffffffffu, ak.w, off);
        }
        if (lane < 4)      *(float4*)(g_Q + (size_t)idx * 16 + lane * 4) = aq;
        else if (lane < 8) *(float4*)(g_K + (size_t)idx * 16 + (lane - 4) * 4) = ak;
    }
    else if (blockIdx.x < QK_BLOCKS + XT_BLOCKS) {
        // ---- Xt transpose tile: X[bf][lc*64 + r][d] -> Xt[bf][d][lc*64 + r]
        int b  = blockIdx.x - QK_BLOCKS;
        int bf = b >> 2, lc = b & 3;
        const float4* src = (const float4*)(X + ((size_t)bf * NT + lc * 64) * DIN);
        for (int i = tid; i < 64 * 16; i += 256) {
            int r = i >> 4, c0 = (i & 15) * 4;
            float4 v = __ldg(&src[i]);
            tsm[r * 65 + c0 + 0] = v.x;
            tsm[r * 65 + c0 + 1] = v.y;
            tsm[r * 65 + c0 + 2] = v.z;
            tsm[r * 65 + c0 + 3] = v.w;
        }
        __syncthreads();
        unsigned* dst = g_Xt + (size_t)bf * (DIN * NT) + lc * 64;
        for (int i = tid; i < 64 * 16; i += 256) {
            int d = i >> 4, r0 = (i & 15) * 4;
            uint4 o;
            o.x = f2tf32(tsm[(r0 + 0) * 65 + d]);
            o.y = f2tf32(tsm[(r0 + 1) * 65 + d]);
            o.z = f2tf32(tsm[(r0 + 2) * 65 + d]);
            o.w = f2tf32(tsm[(r0 + 3) * 65 + d]);
            *(uint4*)(dst + (size_t)d * NT + r0) = o;
        }
    }
    else {
        // ---- Wt transpose tile: W[f][kc*64 + r][o] -> Wt[f][o][kc*64 + r]
        int b  = blockIdx.x - QK_BLOCKS - XT_BLOCKS;
        int f = b >> 3, kc = b & 7;
        const float4* src = (const float4*)(W + ((size_t)f * NK + kc * 64) * DOUT);
        for (int i = tid; i < 64 * 16; i += 256) {
            int r = i >> 4, c0 = (i & 15) * 4;
            float4 v = __ldg(&src[i]);
            tsm[r * 65 + c0 + 0] = v.x;
            tsm[r * 65 + c0 + 1] = v.y;
            tsm[r * 65 + c0 + 2] = v.z;
            tsm[r * 65 + c0 + 3] = v.w;
        }
        __syncthreads();
        unsigned* dst = g_Wt + (size_t)f * (DOUT * NK) + kc * 64;
        for (int i = tid; i < 64 * 16; i += 256) {
            int o = i >> 4, r0 = (i & 15) * 4;
            uint4 ov;
            ov.x = f2tf32(tsm[(r0 + 0) * 65 + o]);
            ov.y = f2tf32(tsm[(r0 + 1) * 65 + o]);
            ov.z = f2tf32(tsm[(r0 + 2) * 65 + o]);
            ov.w = f2tf32(tsm[(r0 + 3) * 65 + o]);
            *(uint4*)(dst + (size_t)o * NK + r0) = ov;
        }
    }
}

// ---------------------------------------------------------------------------
// Kernel 2 (FUSED): scores -> softmax -> P@X^T -> vals@W + b -> Out.
// grid = BF*16 = 512, 512 threads.
// Phase A smem: P[128][260] | Xt[64][260] | Ksm 8*512 | usm 512  (218112 B)
// Phase B overlays: Bw[64][516] | Av[16][516] | red[1024]
// ---------------------------------------------------------------------------
#define SP 260
#define SBW 516
#define SAV 516
#define XT_OFF (128*SP)             // 33280
#define KS_OFF (XT_OFF + 64*SP)     // 49920
#define US_OFF (KS_OFF + 8*512)     // 54016
#define K2_BYTES ((US_OFF + 512)*4) // 218112

__global__ void __launch_bounds__(512, 1)
attn_kernel(const float* __restrict__ ac,
            const float* __restrict__ alpha,
            const float* __restrict__ wkey,
            const float* __restrict__ u,
            const float* __restrict__ Bv,
            float* __restrict__ Out)
{
    extern __shared__ float sm[];
    unsigned* Pb  = (unsigned*)sm;            // [128][SP] tf32 bits
    unsigned* Xtb = (unsigned*)sm + XT_OFF;   // [64][SP]
    float* Ksm = sm + KS_OFF;
    float* usm = sm + US_OFF;
    unsigned* Bw  = (unsigned*)sm;            // [64][SBW]
    unsigned* Av  = (unsigned*)sm + XT_OFF;   // [16][SAV]
    float* red = sm + KS_OFF;                 // [8][32][4]

    int bf   = blockIdx.x >> 4;
    int f    = bf & (NF - 1);
    int t0   = (blockIdx.x & 15) << 4;
    int tid  = threadIdx.x;
    int lane = tid & 31;
    int w    = tid >> 5;

    // ---- stage Xt (uint4), K rows, u ----
    const uint4* Xg4 = (const uint4*)(g_Xt + (size_t)bf * DIN * NT);
    for (int i = tid; i < DIN * NT / 4; i += 512) {
        int d = i >> 6, l4 = (i & 63) * 4;
        *(uint4*)&Xtb[d * SP + l4] = __ldg(&Xg4[i]);
    }
    {
        const float* Kg = g_K + (size_t)bf * (NT * 16);
        for (int i = tid; i < NT * 16; i += 512) {
            float kv = Kg[i];
            int l = i >> 4, h = (i >> 1) & 7, e = i & 1;
            Ksm[h * 512 + l * 2 + e] = kv;
        }
        for (int i = tid; i < NT * 2; i += 512) usm[i] = __ldg(&u[f * (NT * 2) + i]);
    }
    __syncthreads();

    int t     = t0 + w;
    int idx_t = bf * NT + t;
    float alpha_f = __ldg(&alpha[f]);
    float a0c = __ldg(&wkey[f*4+0]), b0c = __ldg(&wkey[f*4+1]);
    float a1c = __ldg(&wkey[f*4+2]), b1c = __ldg(&wkey[f*4+3]);
    float v0 = -alpha_f;

    // ---- scores + softmax; P row = 8*w + h, tf32 bits ----
#pragma unroll
    for (int hp = 0; hp < 4; hp++) {
        int h0 = hp * 2;
        float4 q4 = __ldg((const float4*)(g_Q + (size_t)idx_t * 16 + h0 * 2));
        float4 k4 = __ldg((const float4*)(g_K + (size_t)idx_t * 16 + h0 * 2));
        float v1a = 2.0f * alpha_f * __ldg(&ac[f * NH + h0]);
        float v1b = 2.0f * alpha_f * __ldg(&ac[f * NH + h0 + 1]);
        float qa0 = q4.x + v0, qa1 = q4.y + v1a;
        float A0 = fmaf(qa0, a0c, qa1 * a1c), B0 = fmaf(qa0, b0c, qa1 * b1c);
        float qb0 = q4.z + v0, qb1 = q4.w + v1b;
        float A1 = fmaf(qb0, a0c, qb1 * a1c), B1 = fmaf(qb0, b0c, qb1 * b1c);

        const float* Kh0 = Ksm + h0 * 512;
        const float* Kh1 = Kh0 + 512;
        float s0[8], s1[8], m0 = -3.4e38f, m1 = -3.4e38f;
#pragma unroll
        for (int j = 0; j < 8; j++) {
            int l = j * 32 + lane;
            float2 kv0 = *(const float2*)(Kh0 + l * 2);
            float2 kv1 = *(const float2*)(Kh1 + l * 2);
            float2 uv  = *(const float2*)(usm + l * 2);
            float r = (float)(l - t);
            float base0 = r * fmaf(A0, r, B0) + uv.x * k4.x + uv.y * k4.y;
            float base1 = r * fmaf(A1, r, B1) + uv.x * k4.z + uv.y * k4.w;
            base0 = fmaf(q4.x, kv0.x, base0); base0 = fmaf(q4.y, kv0.y, base0);
            base1 = fmaf(q4.z, kv1.x, base1); base1 = fmaf(q4.w, kv1.y, base1);
            s0[j] = base0; s1[j] = base1;
            m0 = fmaxf(m0, base0); m1 = fmaxf(m1, base1);
        }
#pragma unroll
        for (int o = 16; o; o >>= 1) {
            m0 = fmaxf(m0, __shfl_xor_sync(0xffffffffu, m0, o));
            m1 = fmaxf(m1, __shfl_xor_sync(0xffffffffu, m1, o));
        }
        float sum0 = 0.f, sum1 = 0.f;
#pragma unroll
        for (int j = 0; j < 8; j++) {
            s0[j] = __expf(s0[j] - m0); sum0 += s0[j];
            s1[j] = __expf(s1[j] - m1); sum1 += s1[j];
        }
#pragma unroll
        for (int o = 16; o; o >>= 1) {
            sum0 += __shfl_xor_sync(0xffffffffu, sum0, o);
            sum1 += __shfl_xor_sync(0xffffffffu, sum1, o);
        }
        float inv0 = 1.0f / sum0, inv1 = 1.0f / sum1;
        unsigned* pr0 = Pb + (8 * w + h0) * SP;
#pragma unroll
        for (int j = 0; j < 8; j++) {
            int l = j * 32 + lane;
            pr0[l]      = f2tf32(s0[j] * inv0);
            pr0[SP + l] = f2tf32(s1[j] * inv1);
        }
    }
    __syncthreads();

    // ---- MMA1: D[th=128][d=64] = P @ Xt^T, K = 256 ----
    int g  = lane >> 2;
    int s4 = lane & 3;
    int mi = w & 7;
    int n0 = (w >> 3) * 32;

    const unsigned* aP = Pb + (16 * mi + g) * SP + s4;
    float acc[4][4];
#pragma unroll
    for (int i = 0; i < 4; i++)
#pragma unroll
        for (int j = 0; j < 4; j++) acc[i][j] = 0.f;

#pragma unroll 4
    for (int k0 = 0; k0 < 256; k0 += 8) {
        unsigned a0 = aP[k0];
        unsigned a1 = aP[k0 + 8 * SP];
        unsigned a2 = aP[k0 + 4];
        unsigned a3 = aP[k0 + 8 * SP + 4];
#pragma unroll
        for (int nt = 0; nt < 4; nt++) {
            const unsigned* bB = Xtb + (n0 + 8 * nt + g) * SP + s4 + k0;
            mma8(acc[nt], a0, a1, a2, a3, bB[0], bB[4]);
        }
    }
    __syncthreads();   // P and Xt now dead; overlays become writable

    // ---- phase B staging: Bw = W[f] tf32 (from g_Wt), Av = vals tf32 ----
    {
        const uint4* gw = (const uint4*)(g_Wt + (size_t)f * DOUT * NK);
        for (int i = tid; i < DOUT * NK / 4; i += 512) {
            int o = i >> 7, k4i = (i & 127) * 4;
            uint4 v = __ldg(&gw[i]);
            *(uint4*)&Bw[o * SBW + k4i] = v;
        }
    }
    {
        int thA = 16 * mi + g, thB = thA + 8;
        int tA = thA >> 3, hA = thA & 7;
        int tB = thB >> 3, hB = thB & 7;
#pragma unroll
        for (int nt = 0; nt < 4; nt++) {
            int d = n0 + 8 * nt + 2 * s4;
            uint2 pa, pb;
            pa.x = f2tf32(acc[nt][0]); pa.y = f2tf32(acc[nt][1]);
            pb.x = f2tf32(acc[nt][2]); pb.y = f2tf32(acc[nt][3]);
            *(uint2*)&Av[tA * SAV + hA * 64 + d] = pa;
            *(uint2*)&Av[tB * SAV + hB * 64 + d] = pb;
        }
    }
    __syncthreads();

    // ---- MMA2: Out[16 t][64 o] = Av @ Bw^T + b.  16 warps: n-split 8, k-split 2.
    int ni = w & 7;
    int kh = w >> 3;
    int n0b = ni * 8;
    int kk0 = kh * 256;

    float acc2[4] = {0.f, 0.f, 0.f, 0.f};
    const unsigned* aP2 = Av + g * SAV + s4 + kk0;
    const unsigned* bP2 = Bw + (n0b + g) * SBW + s4 + kk0;
#pragma unroll 8
    for (int k0 = 0; k0 < 256; k0 += 8) {
        unsigned a0 = aP2[k0];
        unsigned a1 = aP2[k0 + 8 * SAV];
        unsigned a2 = aP2[k0 + 4];
        unsigned a3 = aP2[k0 + 8 * SAV + 4];
        mma8(acc2, a0, a1, a2, a3, bP2[k0], bP2[k0 + 4]);
    }
    __syncthreads();   // Ksm region dead -> red
    if (kh == 1) {
        float* r = red + (ni * 32 + lane) * 4;
        r[0] = acc2[0]; r[1] = acc2[1]; r[2] = acc2[2]; r[3] = acc2[3];
    }
    __syncthreads();
    if (kh == 0) {
        const float* r = red + (ni * 32 + lane) * 4;
        acc2[0] += r[0]; acc2[1] += r[1]; acc2[2] += r[2]; acc2[3] += r[3];

        int tA = t0 + g, tB = tA + 8;
        int oc = n0b + 2 * s4;
        float2 ba = __ldg((const float2*)(Bv + ((size_t)(f * NT + tA)) * DOUT + oc));
        float2 bb = __ldg((const float2*)(Bv + ((size_t)(f * NT + tB)) * DOUT + oc));
        *(float2*)(Out + ((size_t)(bf * NT + tA)) * DOUT + oc) =
            make_float2(acc2[0] + ba.x, acc2[1] + ba.y);
        *(float2*)(Out + ((size_t)(bf * NT + tB)) * DOUT + oc) =
            make_float2(acc2[2] + bb.x, acc2[3] + bb.y);
    }
}

// ---------------------------------------------------------------------------
extern "C" void kernel_launch(void* const* d_in, const int* in_sizes, int n_in,
                              void* d_out, int out_size)
{
    const float* X     = (const float*)d_in[0];
    const float* ac    = (const float*)d_in[1];
    const float* alpha = (const float*)d_in[2];
    const float* Wq    = (const float*)d_in[3];
    const float* Wk    = (const float*)d_in[4];
    const float* wkey  = (const float*)d_in[5];
    const float* u     = (const float*)d_in[6];
    const float* W     = (const float*)d_in[7];
    const float* Bv    = (const float*)d_in[8];
    float* Out = (float*)d_out;

    cudaFuncSetAttribute(attn_kernel, cudaFuncAttributeMaxDynamicSharedMemorySize, K2_BYTES);

    pre_kernel<<<QK_BLOCKS + XT_BLOCKS + WT_BLOCKS, 256, 64 * 65 * 4>>>(X, Wq, Wk, W);
    attn_kernel<<<BF * 16, 512, K2_BYTES>>>(ac, alpha, wkey, u, Bv, Out);
}

// round 8
// speedup vs baseline: 2.8431x; 1.1099x over previous
#include <cuda_runtime.h>
#include <cstdint>
#include <cstddef>

#define BS 4
#define NF 8
#define NT 256
#define DIN 64
#define NH 8
#define DOUT 64
#define BF (BS*NF)          // 32
#define NK (NH*DIN)         // 512

// Scratch (allocation-free)
__device__ float g_Q[BF * NT * NH * 2];               // [bf][t][h][e]
__device__ float g_K[BF * NT * NH * 2];
__device__ unsigned g_Xt[(size_t)BF * DIN * NT];      // tf32 bits, [bf][d][phys(l)]
__device__ unsigned g_Wt[(size_t)NF * DOUT * NK];     // tf32 bits, [f][o][phys(k)]

static __device__ __forceinline__ unsigned f2tf32(float v) {
    unsigned t; asm("cvt.rna.tf32.f32 %0, %1;" : "=r"(t) : "f"(v)); return t;
}
static __device__ __forceinline__ uint32_t smem_u32(const void* p) {
    uint32_t a;
    asm("{ .reg .u64 t; cvta.to.shared.u64 t, %1; cvt.u32.u64 %0, t; }" : "=r"(a) : "l"(p));
    return a;
}
#define CP_ASYNC16(dst, src) \
    asm volatile("cp.async.cg.shared.global [%0], [%1], 16;" :: "r"(dst), "l"(src) : "memory")
#define CP_COMMIT()  asm volatile("cp.async.commit_group;" ::: "memory")
#define CP_WAIT0()   asm volatile("cp.async.wait_group 0;" ::: "memory")

static __device__ __forceinline__ void mma8(float* d, unsigned a0, unsigned a1,
                                            unsigned a2, unsigned a3,
                                            unsigned b0, unsigned b1) {
    asm volatile("mma.sync.aligned.m16n8k8.row.col.f32.tf32.tf32.f32 "
        "{%0,%1,%2,%3}, {%4,%5,%6,%7}, {%8,%9}, {%0,%1,%2,%3};"
        : "+f"(d[0]), "+f"(d[1]), "+f"(d[2]), "+f"(d[3])
        : "r"(a0), "r"(a1), "r"(a2), "r"(a3), "r"(b0), "r"(b1));
}

// ---------------------------------------------------------------------------
// Fused pre-kernel: [0,1024) QK; [1024,1152) X->Xt; [1152,1216) W->Wt.
// Transposes write the k-pair-interleaved (phys) layout:
//   phys(k) = (k&~7) + 2*(k&3) + ((k>>2)&1)
// ---------------------------------------------------------------------------
#define QK_BLOCKS 1024
#define XT_BLOCKS 128
#define WT_BLOCKS 64

__global__ void __launch_bounds__(256)
pre_kernel(const float* __restrict__ X,
           const float* __restrict__ Wq,
           const float* __restrict__ Wk,
           const float* __restrict__ W)
{
    extern __shared__ float tsm[];   // [64][65]
    int tid = threadIdx.x;

    if (blockIdx.x < QK_BLOCKS) {
        int idx  = blockIdx.x * 8 + (tid >> 5);
        int lane = tid & 31;
        int t_ft = idx & (NF * NT - 1);

        const float* x = X + (size_t)idx * DIN;
        float x0 = __ldg(&x[lane]);
        float x1 = __ldg(&x[lane + 32]);

        int dq = lane >> 2;
        const float4* Wq4 = (const float4*)(Wq + (size_t)t_ft * (DIN * 16));
        const float4* Wk4 = (const float4*)(Wk + (size_t)t_ft * (DIN * 16));

        float4 wq[8], wk[8];
#pragma unroll
        for (int i = 0; i < 8; i++) {
            wq[i] = __ldg(&Wq4[i * 32 + lane]);
            wk[i] = __ldg(&Wk4[i * 32 + lane]);
        }
        float4 aq = {0,0,0,0}, ak = {0,0,0,0};
#pragma unroll
        for (int i = 0; i < 8; i++) {
            int dsel = (i & 3) * 8 + dq;
            float xv = __shfl_sync(0xffffffffu, (i < 4) ? x0 : x1, dsel);
            aq.x = fmaf(xv, wq[i].x, aq.x); aq.y = fmaf(xv, wq[i].y, aq.y);
            aq.z = fmaf(xv, wq[i].z, aq.z); aq.w = fmaf(xv, wq[i].w, aq.w);
            ak.x = fmaf(xv, wk[i].x, ak.x); ak.y = fmaf(xv, wk[i].y, ak.y);
            ak.z = fmaf(xv, wk[i].z, ak.z); ak.w = fmaf(xv, wk[i].w, ak.w);
        }
#pragma unroll
        for (int off = 16; off >= 4; off >>= 1) {
            aq.x += __shfl_xor_sync(0xffffffffu, aq.x, off);
            aq.y += __shfl_xor_sync(0xffffffffu, aq.y, off);
            aq.z += __shfl_xor_sync(0xffffffffu, aq.z, off);
            aq.w += __shfl_xor_sync(0xffffffffu, aq.w, off);
            ak.x += __shfl_xor_sync(0xffffffffu, ak.x, off);
            ak.y += __shfl_xor_sync(0xffffffffu, ak.y, off);
            ak.z += __shfl_xor_sync(0xffffffffu, ak.z, off);
            ak.w += __shfl_xor_sync(0xffffffffu, ak.w, off);
        }
        if (lane < 4)      *(float4*)(g_Q + (size_t)idx * 16 + lane * 4) = aq;
        else if (lane < 8) *(float4*)(g_K + (size_t)idx * 16 + (lane - 4) * 4) = ak;
    }
    else if (blockIdx.x < QK_BLOCKS + XT_BLOCKS) {
        // X[bf][lc*64 + r][d] -> g_Xt[bf][d][phys(lc*64 + r)]
        int b  = blockIdx.x - QK_BLOCKS;
        int bf = b >> 2, lc = b & 3;
        const float4* src = (const float4*)(X + ((size_t)bf * NT + lc * 64) * DIN);
        for (int i = tid; i < 64 * 16; i += 256) {
            int r = i >> 4, c0 = (i & 15) * 4;
            float4 v = __ldg(&src[i]);
            tsm[r * 65 + c0 + 0] = v.x;
            tsm[r * 65 + c0 + 1] = v.y;
            tsm[r * 65 + c0 + 2] = v.z;
            tsm[r * 65 + c0 + 3] = v.w;
        }
        __syncthreads();
        unsigned* dst = g_Xt + (size_t)bf * (DIN * NT) + lc * 64;
        // FIXED: 32 uint2 per d-row (64 words), not 16
        for (int i = tid; i < 64 * 32; i += 256) {
            int d = i >> 5, p = i & 31;
            int g8 = p >> 2, s = p & 3;
            int la = g8 * 8 + s, lb = la + 4;
            uint2 o;
            o.x = f2tf32(tsm[la * 65 + d]);
            o.y = f2tf32(tsm[lb * 65 + d]);
            *(uint2*)(dst + (size_t)d * NT + g8 * 8 + 2 * s) = o;
        }
    }
    else {
        // W[f][kc*64 + r][o] -> g_Wt[f][o][phys(kc*64 + r)]
        int b  = blockIdx.x - QK_BLOCKS - XT_BLOCKS;
        int f = b >> 3, kc = b & 7;
        const float4* src = (const float4*)(W + ((size_t)f * NK + kc * 64) * DOUT);
        for (int i = tid; i < 64 * 16; i += 256) {
            int r = i >> 4, c0 = (i & 15) * 4;
            float4 v = __ldg(&src[i]);
            tsm[r * 65 + c0 + 0] = v.x;
            tsm[r * 65 + c0 + 1] = v.y;
            tsm[r * 65 + c0 + 2] = v.z;
            tsm[r * 65 + c0 + 3] = v.w;
        }
        __syncthreads();
        unsigned* dst = g_Wt + (size_t)f * (DOUT * NK) + kc * 64;
        // FIXED: 32 uint2 per o-row (64 words), not 16
        for (int i = tid; i < 64 * 32; i += 256) {
            int o = i >> 5, p = i & 31;
            int g8 = p >> 2, s = p & 3;
            int ka = g8 * 8 + s, kb = ka + 4;
            uint2 ov;
            ov.x = f2tf32(tsm[ka * 65 + o]);
            ov.y = f2tf32(tsm[kb * 65 + o]);
            *(uint2*)(dst + (size_t)o * NK + g8 * 8 + 2 * s) = ov;
        }
    }
}

// ---------------------------------------------------------------------------
// FUSED attn: scores -> softmax -> P@X^T -> vals@W + b -> Out.
// grid = BF*16 = 512, 512 threads.
// smem words: P[128][264] | Xt[64][264] | Ksm 8*512 | usm 512  (221184 B)
// Overlays: Av[16][520] over Xt; red[1024] over Ksm.
// ---------------------------------------------------------------------------
#define SP 264
#define SAV 520
#define XT_OFF (128*SP)              // 33792
#define KS_OFF (XT_OFF + 64*SP)      // 50688
#define US_OFF (KS_OFF + 8*512)      // 54784
#define K2_BYTES ((US_OFF + 512)*4)  // 221184

__global__ void __launch_bounds__(512, 1)
attn_kernel(const float* __restrict__ ac,
            const float* __restrict__ alpha,
            const float* __restrict__ wkey,
            const float* __restrict__ u,
            const float* __restrict__ Bv,
            float* __restrict__ Out)
{
    extern __shared__ float sm[];
    unsigned* Pb  = (unsigned*)sm;            // [128][SP] tf32 bits (phys cols)
    unsigned* Xtb = (unsigned*)sm + XT_OFF;   // [64][SP] (phys cols)
    float* Ksm = sm + KS_OFF;
    float* usm = sm + US_OFF;
    unsigned* Av  = (unsigned*)sm + XT_OFF;   // [16][SAV] overlay
    float* red = sm + KS_OFF;                 // [8][32][4] overlay

    int bf   = blockIdx.x >> 4;
    int f    = bf & (NF - 1);
    int t0   = (blockIdx.x & 15) << 4;
    int tid  = threadIdx.x;
    int lane = tid & 31;
    int w    = tid >> 5;
    uint32_t smb = smem_u32(sm);

    // ---- cp.async Xt (overlaps all of softmax) ----
    {
        const unsigned* Xg = g_Xt + (size_t)bf * DIN * NT;
#pragma unroll
        for (int c = 0; c < 8; c++) {
            int i = tid + c * 512;                 // uint4 index
            int d = i >> 6, l4 = (i & 63) * 4;
            uint32_t dst = smb + (uint32_t)(XT_OFF + d * SP + l4) * 4;
            CP_ASYNC16(dst, Xg + (size_t)d * NT + l4);
        }
        CP_COMMIT();
    }
    // ---- stage K rows + u ----
    {
        const float* Kg = g_K + (size_t)bf * (NT * 16);
        for (int i = tid; i < NT * 16; i += 512) {
            float kv = Kg[i];
            int l = i >> 4, h = (i >> 1) & 7, e = i & 1;
            Ksm[h * 512 + l * 2 + e] = kv;
        }
        for (int i = tid; i < NT * 2; i += 512) usm[i] = __ldg(&u[f * (NT * 2) + i]);
    }
    __syncthreads();   // K/u visible (Xt may still be in flight)

    int t     = t0 + w;
    int idx_t = bf * NT + t;
    float alpha_f = __ldg(&alpha[f]);
    float a0c = __ldg(&wkey[f*4+0]), b0c = __ldg(&wkey[f*4+1]);
    float a1c = __ldg(&wkey[f*4+2]), b1c = __ldg(&wkey[f*4+3]);
    float v0 = -alpha_f;

    // ---- scores + softmax; P row = 8*w + h, phys cols ----
#pragma unroll
    for (int hp = 0; hp < 4; hp++) {
        int h0 = hp * 2;
        float4 q4 = __ldg((const float4*)(g_Q + (size_t)idx_t * 16 + h0 * 2));
        float4 k4 = __ldg((const float4*)(g_K + (size_t)idx_t * 16 + h0 * 2));
        float v1a = 2.0f * alpha_f * __ldg(&ac[f * NH + h0]);
        float v1b = 2.0f * alpha_f * __ldg(&ac[f * NH + h0 + 1]);
        float qa0 = q4.x + v0, qa1 = q4.y + v1a;
        float A0 = fmaf(qa0, a0c, qa1 * a1c), B0 = fmaf(qa0, b0c, qa1 * b1c);
        float qb0 = q4.z + v0, qb1 = q4.w + v1b;
        float A1 = fmaf(qb0, a0c, qb1 * a1c), B1 = fmaf(qb0, b0c, qb1 * b1c);

        const float* Kh0 = Ksm + h0 * 512;
        const float* Kh1 = Kh0 + 512;
        float s0[8], s1[8], m0 = -3.4e38f, m1 = -3.4e38f;
#pragma unroll
        for (int j = 0; j < 8; j++) {
            int l = j * 32 + lane;
            float2 kv0 = *(const float2*)(Kh0 + l * 2);
            float2 kv1 = *(const float2*)(Kh1 + l * 2);
            float2 uv  = *(const float2*)(usm + l * 2);
            float r = (float)(l - t);
            float base0 = r * fmaf(A0, r, B0) + uv.x * k4.x + uv.y * k4.y;
            float base1 = r * fmaf(A1, r, B1) + uv.x * k4.z + uv.y * k4.w;
            base0 = fmaf(q4.x, kv0.x, base0); base0 = fmaf(q4.y, kv0.y, base0);
            base1 = fmaf(q4.z, kv1.x, base1); base1 = fmaf(q4.w, kv1.y, base1);
            s0[j] = base0; s1[j] = base1;
            m0 = fmaxf(m0, base0); m1 = fmaxf(m1, base1);
        }
#pragma unroll
        for (int o = 16; o; o >>= 1) {
            m0 = fmaxf(m0, __shfl_xor_sync(0xffffffffu, m0, o));
            m1 = fmaxf(m1, __shfl_xor_sync(0xffffffffu, m1, o));
        }
        float sum0 = 0.f, sum1 = 0.f;
#pragma unroll
        for (int j = 0; j < 8; j++) {
            s0[j] = __expf(s0[j] - m0); sum0 += s0[j];
            s1[j] = __expf(s1[j] - m1); sum1 += s1[j];
        }
#pragma unroll
        for (int o = 16; o; o >>= 1) {
            sum0 += __shfl_xor_sync(0xffffffffu, sum0, o);
            sum1 += __shfl_xor_sync(0xffffffffu, sum1, o);
        }
        float inv0 = 1.0f / sum0, inv1 = 1.0f / sum1;
        unsigned* pr0 = Pb + (8 * w + h0) * SP;
#pragma unroll
        for (int j = 0; j < 8; j++) {
            int k = j * 32 + lane;
            int kp = (k & ~7) + 2 * (k & 3) + ((k >> 2) & 1);
            pr0[kp]      = f2tf32(s0[j] * inv0);
            pr0[SP + kp] = f2tf32(s1[j] * inv1);
        }
    }
    CP_WAIT0();
    __syncthreads();   // P + Xt visible

    // ---- MMA1: D[th=128][d=64] = P @ Xt^T, K=256, LDS.64 fragments ----
    int g  = lane >> 2;
    int s4 = lane & 3;
    int mi = w & 7;
    int n0 = (w >> 3) * 32;

    const uint2* aR0 = (const uint2*)(Pb + (16 * mi + g) * SP) + s4;
    const uint2* aR1 = (const uint2*)(Pb + (16 * mi + g + 8) * SP) + s4;
    const uint2* bR0 = (const uint2*)(Xtb + (n0 + 0 + g) * SP) + s4;
    const uint2* bR1 = (const uint2*)(Xtb + (n0 + 8 + g) * SP) + s4;
    const uint2* bR2 = (const uint2*)(Xtb + (n0 + 16 + g) * SP) + s4;
    const uint2* bR3 = (const uint2*)(Xtb + (n0 + 24 + g) * SP) + s4;

    float acc[4][4];
#pragma unroll
    for (int i = 0; i < 4; i++)
#pragma unroll
        for (int j = 0; j < 4; j++) acc[i][j] = 0.f;

#pragma unroll 4
    for (int k0 = 0; k0 < 256; k0 += 8) {
        int ki = k0 >> 1;
        uint2 a02 = aR0[ki], a13 = aR1[ki];
        uint2 b0 = bR0[ki], b1 = bR1[ki], b2 = bR2[ki], b3 = bR3[ki];
        mma8(acc[0], a02.x, a13.x, a02.y, a13.y, b0.x, b0.y);
        mma8(acc[1], a02.x, a13.x, a02.y, a13.y, b1.x, b1.y);
        mma8(acc[2], a02.x, a13.x, a02.y, a13.y, b2.x, b2.y);
        mma8(acc[3], a02.x, a13.x, a02.y, a13.y, b3.x, b3.y);
    }
    __syncthreads();   // P/Xt dead; Av overlay writable

    // ---- Av = vals tf32, rows = t local, cols = h*64+d (phys) ----
    {
        int thA = 16 * mi + g, thB = thA + 8;
        int tA = thA >> 3, hA = thA & 7;
        int tB = thB >> 3, hB = thB & 7;
        int j = 2 * s4;
        int p0 = 2 * (j & 3) + ((j >> 2) & 1);
        int p1 = 2 * ((j + 1) & 3) + (((j + 1) >> 2) & 1);
#pragma unroll
        for (int nt = 0; nt < 4; nt++) {
            int kbaseA = hA * 64 + ((n0 + 8 * nt + 2 * s4) & ~7);
            int kbaseB = hB * 64 + ((n0 + 8 * nt + 2 * s4) & ~7);
            Av[tA * SAV + kbaseA + p0] = f2tf32(acc[nt][0]);
            Av[tA * SAV + kbaseA + p1] = f2tf32(acc[nt][1]);
            Av[tB * SAV + kbaseB + p0] = f2tf32(acc[nt][2]);
            Av[tB * SAV + kbaseB + p1] = f2tf32(acc[nt][3]);
        }
    }
    __syncthreads();

    // ---- MMA2: Out[16 t][64 o] = Av @ Wt^T + b.  n-split 8 x k-split 2.
    // B fragments straight from L2-resident g_Wt (LDG.64).
    int ni = w & 7;
    int kh = w >> 3;
    int n0b = ni * 8;
    int kbase = kh * 256;

    float acc2[4] = {0.f, 0.f, 0.f, 0.f};
    const uint2* aP0 = (const uint2*)(Av + g * SAV) + s4;
    const uint2* aP1 = (const uint2*)(Av + (g + 8) * SAV) + s4;
    const uint2* wR  = (const uint2*)(g_Wt + (size_t)f * DOUT * NK + (size_t)(n0b + g) * NK) + s4;
#pragma unroll 8
    for (int k0 = kbase; k0 < kbase + 256; k0 += 8) {
        int ki = k0 >> 1;
        uint2 a02 = aP0[ki], a13 = aP1[ki];
        uint2 b01 = __ldg(&wR[ki]);
        mma8(acc2, a02.x, a13.x, a02.y, a13.y, b01.x, b01.y);
    }
    __syncthreads();   // Ksm dead -> red
    if (kh == 1) {
        float* r = red + (ni * 32 + lane) * 4;
        r[0] = acc2[0]; r[1] = acc2[1]; r[2] = acc2[2]; r[3] = acc2[3];
    }
    __syncthreads();
    if (kh == 0) {
        const float* r = red + (ni * 32 + lane) * 4;
        acc2[0] += r[0]; acc2[1] += r[1]; acc2[2] += r[2]; acc2[3] += r[3];

        int tA = t0 + g, tB = tA + 8;
        int oc = n0b + 2 * s4;
        float2 ba = __ldg((const float2*)(Bv + ((size_t)(f * NT + tA)) * DOUT + oc));
        float2 bb = __ldg((const float2*)(Bv + ((size_t)(f * NT + tB)) * DOUT + oc));
        *(float2*)(Out + ((size_t)(bf * NT + tA)) * DOUT + oc) =
            make_float2(acc2[0] + ba.x, acc2[1] + ba.y);
        *(float2*)(Out + ((size_t)(bf * NT + tB)) * DOUT + oc) =
            make_float2(acc2[2] + bb.x, acc2[3] + bb.y);
    }
}

// ---------------------------------------------------------------------------
extern "C" void kernel_launch(void* const* d_in, const int* in_sizes, int n_in,
                              void* d_out, int out_size)
{
    const float* X     = (const float*)d_in[0];
    const float* ac    = (const float*)d_in[1];
    const float* alpha = (const float*)d_in[2];
    const float* Wq    = (const float*)d_in[3];
    const float* Wk    = (const float*)d_in[4];
    const float* wkey  = (const float*)d_in[5];
    const float* u     = (const float*)d_in[6];
    const float* W     = (const float*)d_in[7];
    const float* Bv    = (const float*)d_in[8];
    float* Out = (float*)d_out;

    cudaFuncSetAttribute(attn_kernel, cudaFuncAttributeMaxDynamicSharedMemorySize, K2_BYTES);

    pre_kernel<<<QK_BLOCKS + XT_BLOCKS + WT_BLOCKS, 256, 64 * 65 * 4>>>(X, Wq, Wk, W);
    attn_kernel<<<BF * 16, 512, K2_BYTES>>>(ac, alpha, wkey, u, Bv, Out);
}

// round 9
// speedup vs baseline: 3.0271x; 1.0647x over previous
#include <cuda_runtime.h>
#include <cstdint>
#include <cstddef>

#define BS 4
#define NF 8
#define NT 256
#define DIN 64
#define NH 8
#define DOUT 64
#define BF (BS*NF)          // 32
#define NK (NH*DIN)         // 512

// Scratch (allocation-free)
__device__ float g_Q[BF * NT * NH * 2];               // [bf][t][h][e]
__device__ float g_K[BF * NT * NH * 2];
__device__ unsigned g_Xt[(size_t)BF * DIN * NT];      // tf32 bits, [bf][d][phys(l)]
__device__ unsigned g_Wt[(size_t)NF * DOUT * NK];     // tf32 bits, [f][o][phys(k)]

static __device__ __forceinline__ unsigned f2tf32(float v) {
    unsigned t; asm("cvt.rna.tf32.f32 %0, %1;" : "=r"(t) : "f"(v)); return t;
}
static __device__ __forceinline__ uint32_t smem_u32(const void* p) {
    uint32_t a;
    asm("{ .reg .u64 t; cvta.to.shared.u64 t, %1; cvt.u32.u64 %0, t; }" : "=r"(a) : "l"(p));
    return a;
}
#define CP_ASYNC16(dst, src) \
    asm volatile("cp.async.cg.shared.global [%0], [%1], 16;" :: "r"(dst), "l"(src) : "memory")
#define CP_COMMIT()  asm volatile("cp.async.commit_group;" ::: "memory")
#define CP_WAIT0()   asm volatile("cp.async.wait_group 0;" ::: "memory")
#define CP_WAIT1()   asm volatile("cp.async.wait_group 1;" ::: "memory")

static __device__ __forceinline__ void mma8(float* d, unsigned a0, unsigned a1,
                                            unsigned a2, unsigned a3,
                                            unsigned b0, unsigned b1) {
    asm volatile("mma.sync.aligned.m16n8k8.row.col.f32.tf32.tf32.f32 "
        "{%0,%1,%2,%3}, {%4,%5,%6,%7}, {%8,%9}, {%0,%1,%2,%3};"
        : "+f"(d[0]), "+f"(d[1]), "+f"(d[2]), "+f"(d[3])
        : "r"(a0), "r"(a1), "r"(a2), "r"(a3), "r"(b0), "r"(b1));
}

// warp-wide float max via redux.sync on order-preserving uint encoding
static __device__ __forceinline__ float warp_max_f32(float x) {
    unsigned b = __float_as_uint(x);
    unsigned e = b ^ (unsigned)(((int)b >> 31) | 0x80000000);
    unsigned r;
    asm volatile("redux.sync.max.u32 %0, %1, 0xffffffff;" : "=r"(r) : "r"(e));
    unsigned bb = ((int)r < 0) ? (r ^ 0x80000000u) : ~r;
    return __uint_as_float(bb);
}

// ---------------------------------------------------------------------------
// Fused pre-kernel: [0,1024) QK; [1024,1152) X->Xt; [1152,1216) W->Wt.
// phys(k) = (k&~7) + 2*(k&3) + ((k>>2)&1)
// ---------------------------------------------------------------------------
#define QK_BLOCKS 1024
#define XT_BLOCKS 128
#define WT_BLOCKS 64

__global__ void __launch_bounds__(256)
pre_kernel(const float* __restrict__ X,
           const float* __restrict__ Wq,
           const float* __restrict__ Wk,
           const float* __restrict__ W)
{
    extern __shared__ float tsm[];   // [64][65]
    int tid = threadIdx.x;

    if (blockIdx.x < QK_BLOCKS) {
        int idx  = blockIdx.x * 8 + (tid >> 5);
        int lane = tid & 31;
        int t_ft = idx & (NF * NT - 1);

        const float* x = X + (size_t)idx * DIN;
        float x0 = __ldg(&x[lane]);
        float x1 = __ldg(&x[lane + 32]);

        int dq = lane >> 2;
        const float4* Wq4 = (const float4*)(Wq + (size_t)t_ft * (DIN * 16));
        const float4* Wk4 = (const float4*)(Wk + (size_t)t_ft * (DIN * 16));

        float4 wq[8], wk[8];
#pragma unroll
        for (int i = 0; i < 8; i++) {
            wq[i] = __ldg(&Wq4[i * 32 + lane]);
            wk[i] = __ldg(&Wk4[i * 32 + lane]);
        }
        float4 aq = {0,0,0,0}, ak = {0,0,0,0};
#pragma unroll
        for (int i = 0; i < 8; i++) {
            int dsel = (i & 3) * 8 + dq;
            float xv = __shfl_sync(0xffffffffu, (i < 4) ? x0 : x1, dsel);
            aq.x = fmaf(xv, wq[i].x, aq.x); aq.y = fmaf(xv, wq[i].y, aq.y);
            aq.z = fmaf(xv, wq[i].z, aq.z); aq.w = fmaf(xv, wq[i].w, aq.w);
            ak.x = fmaf(xv, wk[i].x, ak.x); ak.y = fmaf(xv, wk[i].y, ak.y);
            ak.z = fmaf(xv, wk[i].z, ak.z); ak.w = fmaf(xv, wk[i].w, ak.w);
        }
#pragma unroll
        for (int off = 16; off >= 4; off >>= 1) {
            aq.x += __shfl_xor_sync(0xffffffffu, aq.x, off);
            aq.y += __shfl_xor_sync(0xffffffffu, aq.y, off);
            aq.z += __shfl_xor_sync(0xffffffffu, aq.z, off);
            aq.w += __shfl_xor_sync(0xffffffffu, aq.w, off);
            ak.x += __shfl_xor_sync(0xffffffffu, ak.x, off);
            ak.y += __shfl_xor_sync(0xffffffffu, ak.y, off);
            ak.z += __shfl_xor_sync(0xffffffffu, ak.z, off);
            ak.w += __shfl_xor_sync(0xffffffffu, ak.w, off);
        }
        if (lane < 4)      *(float4*)(g_Q + (size_t)idx * 16 + lane * 4) = aq;
        else if (lane < 8) *(float4*)(g_K + (size_t)idx * 16 + (lane - 4) * 4) = ak;
    }
    else if (blockIdx.x < QK_BLOCKS + XT_BLOCKS) {
        int b  = blockIdx.x - QK_BLOCKS;
        int bf = b >> 2, lc = b & 3;
        const float4* src = (const float4*)(X + ((size_t)bf * NT + lc * 64) * DIN);
        for (int i = tid; i < 64 * 16; i += 256) {
            int r = i >> 4, c0 = (i & 15) * 4;
            float4 v = __ldg(&src[i]);
            tsm[r * 65 + c0 + 0] = v.x;
            tsm[r * 65 + c0 + 1] = v.y;
            tsm[r * 65 + c0 + 2] = v.z;
            tsm[r * 65 + c0 + 3] = v.w;
        }
        __syncthreads();
        unsigned* dst = g_Xt + (size_t)bf * (DIN * NT) + lc * 64;
        for (int i = tid; i < 64 * 32; i += 256) {
            int d = i >> 5, p = i & 31;
            int g8 = p >> 2, s = p & 3;
            int la = g8 * 8 + s, lb = la + 4;
            uint2 o;
            o.x = f2tf32(tsm[la * 65 + d]);
            o.y = f2tf32(tsm[lb * 65 + d]);
            *(uint2*)(dst + (size_t)d * NT + g8 * 8 + 2 * s) = o;
        }
    }
    else {
        int b  = blockIdx.x - QK_BLOCKS - XT_BLOCKS;
        int f = b >> 3, kc = b & 7;
        const float4* src = (const float4*)(W + ((size_t)f * NK + kc * 64) * DOUT);
        for (int i = tid; i < 64 * 16; i += 256) {
            int r = i >> 4, c0 = (i & 15) * 4;
            float4 v = __ldg(&src[i]);
            tsm[r * 65 + c0 + 0] = v.x;
            tsm[r * 65 + c0 + 1] = v.y;
            tsm[r * 65 + c0 + 2] = v.z;
            tsm[r * 65 + c0 + 3] = v.w;
        }
        __syncthreads();
        unsigned* dst = g_Wt + (size_t)f * (DOUT * NK) + kc * 64;
        for (int i = tid; i < 64 * 32; i += 256) {
            int o = i >> 5, p = i & 31;
            int g8 = p >> 2, s = p & 3;
            int ka = g8 * 8 + s, kb = ka + 4;
            uint2 ov;
            ov.x = f2tf32(tsm[ka * 65 + o]);
            ov.y = f2tf32(tsm[kb * 65 + o]);
            *(uint2*)(dst + (size_t)o * NK + g8 * 8 + 2 * s) = ov;
        }
    }
}

// ---------------------------------------------------------------------------
// FUSED attn: scores -> softmax(raw exp) -> P@X^T -> (x inv) -> vals@W + b.
// grid = BF*16 = 512, 512 threads.
// smem words: P[128][264] | Xt[64][264] | Ksm4[4][256]f4 | invsm[128]
// Overlays: Av[16][520] over Xt; red[1024] over Ksm.
// ---------------------------------------------------------------------------
#define SP 264
#define SAV 520
#define XT_OFF (128*SP)              // 33792
#define KS_OFF (XT_OFF + 64*SP)      // 50688 (16B aligned: 50688*4 % 16 == 0)
#define INV_OFF (KS_OFF + 4096)      // 54784
#define K2_BYTES ((INV_OFF + 128)*4) // 219648

__global__ void __launch_bounds__(512, 1)
attn_kernel(const float* __restrict__ ac,
            const float* __restrict__ alpha,
            const float* __restrict__ wkey,
            const float* __restrict__ u,
            const float* __restrict__ Bv,
            float* __restrict__ Out)
{
    extern __shared__ float sm[];
    unsigned* Pb  = (unsigned*)sm;            // [128][SP] tf32 bits (phys cols)
    unsigned* Xtb = (unsigned*)sm + XT_OFF;   // [64][SP] (phys cols)
    const float4* Ksm4 = (const float4*)(sm + KS_OFF);  // [4 hp][256 l]
    float* invsm = sm + INV_OFF;              // [128]
    unsigned* Av  = (unsigned*)sm + XT_OFF;   // [16][SAV] overlay
    float* red = sm + KS_OFF;                 // [8][32][4] overlay (post-softmax)

    int bf   = blockIdx.x >> 4;
    int f    = bf & (NF - 1);
    int t0   = (blockIdx.x & 15) << 4;
    int tid  = threadIdx.x;
    int lane = tid & 31;
    int w    = tid >> 5;
    uint32_t smb = smem_u32(sm);

    // ---- cp.async K (group 0) then Xt (group 1) ----
    {
        const float4* Kg4 = (const float4*)(g_K + (size_t)bf * (NT * 16));
#pragma unroll
        for (int c = 0; c < 2; c++) {
            int i = tid + c * 512;            // [0,1024): hp = i>>8, l = i&255
            int hp = i >> 8, l = i & 255;
            uint32_t dst = smb + (uint32_t)(KS_OFF * 4 + (hp * 256 + l) * 16);
            CP_ASYNC16(dst, Kg4 + l * 4 + hp);
        }
        CP_COMMIT();
        const unsigned* Xg = g_Xt + (size_t)bf * DIN * NT;
#pragma unroll
        for (int c = 0; c < 8; c++) {
            int i = tid + c * 512;            // uint4 index
            int d = i >> 6, l4 = (i & 63) * 4;
            uint32_t dst = smb + (uint32_t)(XT_OFF + d * SP + l4) * 4;
            CP_ASYNC16(dst, Xg + (size_t)d * NT + l4);
        }
        CP_COMMIT();
    }

    int t     = t0 + w;
    int idx_t = bf * NT + t;
    float alpha_f = __ldg(&alpha[f]);
    float a0c = __ldg(&wkey[f*4+0]), b0c = __ldg(&wkey[f*4+1]);
    float a1c = __ldg(&wkey[f*4+2]), b1c = __ldg(&wkey[f*4+3]);
    float v0 = -alpha_f;

    // u cached in registers (L2 broadcast across blocks)
    float2 uvj[8];
#pragma unroll
    for (int j = 0; j < 8; j++)
        uvj[j] = __ldg((const float2*)(u + (size_t)f * (NT * 2) + (j * 32 + lane) * 2));
    float rbase = (float)(lane - t);
    int pbase = (lane & ~7) + 2 * (lane & 3) + ((lane >> 2) & 1);

    CP_WAIT1();          // K staged (Xt may still be in flight)
    __syncthreads();

    // ---- scores + softmax (raw exp stored; inv deferred) ----
#pragma unroll
    for (int hp = 0; hp < 4; hp++) {
        int h0 = hp * 2;
        float4 q4 = __ldg((const float4*)(g_Q + (size_t)idx_t * 16 + h0 * 2));
        float4 k4 = __ldg((const float4*)(g_K + (size_t)idx_t * 16 + h0 * 2));
        float v1a = 2.0f * alpha_f * __ldg(&ac[f * NH + h0]);
        float v1b = 2.0f * alpha_f * __ldg(&ac[f * NH + h0 + 1]);
        float qa0 = q4.x + v0, qa1 = q4.y + v1a;
        float A0 = fmaf(qa0, a0c, qa1 * a1c), B0 = fmaf(qa0, b0c, qa1 * b1c);
        float qb0 = q4.z + v0, qb1 = q4.w + v1b;
        float A1 = fmaf(qb0, a0c, qb1 * a1c), B1 = fmaf(qb0, b0c, qb1 * b1c);

        const float4* Kh = Ksm4 + hp * 256;
        float s0[8], s1[8], m0 = -3.4e38f, m1 = -3.4e38f;
#pragma unroll
        for (int j = 0; j < 8; j++) {
            float4 kv = Kh[j * 32 + lane];         // (kh0e0,kh0e1,kh1e0,kh1e1)
            float r = rbase + 32.0f * j;
            float ut0 = fmaf(uvj[j].x, k4.x, uvj[j].y * k4.y);
            float ut1 = fmaf(uvj[j].x, k4.z, uvj[j].y * k4.w);
            float base0 = fmaf(r, fmaf(A0, r, B0), ut0);
            float base1 = fmaf(r, fmaf(A1, r, B1), ut1);
            base0 = fmaf(q4.x, kv.x, base0); base0 = fmaf(q4.y, kv.y, base0);
            base1 = fmaf(q4.z, kv.z, base1); base1 = fmaf(q4.w, kv.w, base1);
            s0[j] = base0; s1[j] = base1;
            m0 = fmaxf(m0, base0); m1 = fmaxf(m1, base1);
        }
        m0 = warp_max_f32(m0);
        m1 = warp_max_f32(m1);

        unsigned* pr0 = Pb + (8 * w + h0) * SP;
        float sum0 = 0.f, sum1 = 0.f;
#pragma unroll
        for (int j = 0; j < 8; j++) {
            float e0 = __expf(s0[j] - m0);
            float e1 = __expf(s1[j] - m1);
            pr0[j * 32 + pbase]      = f2tf32(e0);
            pr0[SP + j * 32 + pbase] = f2tf32(e1);
            sum0 += e0; sum1 += e1;
        }
#pragma unroll
        for (int o = 16; o; o >>= 1) {
            sum0 += __shfl_xor_sync(0xffffffffu, sum0, o);
            sum1 += __shfl_xor_sync(0xffffffffu, sum1, o);
        }
        if (lane == 0) {
            invsm[8 * w + h0]     = 1.0f / sum0;
            invsm[8 * w + h0 + 1] = 1.0f / sum1;
        }
    }
    CP_WAIT0();
    __syncthreads();   // P + Xt + invsm visible

    // ---- MMA1: D[th=128][d=64] = P @ Xt^T, K=256, LDS.64 fragments ----
    int g  = lane >> 2;
    int s4 = lane & 3;
    int mi = w & 7;
    int n0 = (w >> 3) * 32;

    const uint2* aR0 = (const uint2*)(Pb + (16 * mi + g) * SP) + s4;
    const uint2* aR1 = (const uint2*)(Pb + (16 * mi + g + 8) * SP) + s4;
    const uint2* bR0 = (const uint2*)(Xtb + (n0 + 0 + g) * SP) + s4;
    const uint2* bR1 = (const uint2*)(Xtb + (n0 + 8 + g) * SP) + s4;
    const uint2* bR2 = (const uint2*)(Xtb + (n0 + 16 + g) * SP) + s4;
    const uint2* bR3 = (const uint2*)(Xtb + (n0 + 24 + g) * SP) + s4;

    float acc[4][4];
#pragma unroll
    for (int i = 0; i < 4; i++)
#pragma unroll
        for (int j = 0; j < 4; j++) acc[i][j] = 0.f;

#pragma unroll 4
    for (int k0 = 0; k0 < 256; k0 += 8) {
        int ki = k0 >> 1;
        uint2 a02 = aR0[ki], a13 = aR1[ki];
        uint2 b0 = bR0[ki], b1 = bR1[ki], b2 = bR2[ki], b3 = bR3[ki];
        mma8(acc[0], a02.x, a13.x, a02.y, a13.y, b0.x, b0.y);
        mma8(acc[1], a02.x, a13.x, a02.y, a13.y, b1.x, b1.y);
        mma8(acc[2], a02.x, a13.x, a02.y, a13.y, b2.x, b2.y);
        mma8(acc[3], a02.x, a13.x, a02.y, a13.y, b3.x, b3.y);
    }

    // normalization factors for this thread's two rows
    int thA = 16 * mi + g, thB = thA + 8;
    float invA = invsm[thA], invB = invsm[thB];
    __syncthreads();   // P/Xt dead; Av overlay writable

    // ---- Av = vals tf32 (normalized), rows = t local, cols = h*64+d (phys) ----
    {
        int tA = thA >> 3, hA = thA & 7;
        int tB = thB >> 3, hB = thB & 7;
        int j = 2 * s4;
        int p0 = 2 * (j & 3) + ((j >> 2) & 1);
        int p1 = 2 * ((j + 1) & 3) + (((j + 1) >> 2) & 1);
#pragma unroll
        for (int nt = 0; nt < 4; nt++) {
            int kbaseA = hA * 64 + ((n0 + 8 * nt + 2 * s4) & ~7);
            int kbaseB = hB * 64 + ((n0 + 8 * nt + 2 * s4) & ~7);
            Av[tA * SAV + kbaseA + p0] = f2tf32(acc[nt][0] * invA);
            Av[tA * SAV + kbaseA + p1] = f2tf32(acc[nt][1] * invA);
            Av[tB * SAV + kbaseB + p0] = f2tf32(acc[nt][2] * invB);
            Av[tB * SAV + kbaseB + p1] = f2tf32(acc[nt][3] * invB);
        }
    }
    __syncthreads();

    // ---- MMA2: Out[16 t][64 o] = Av @ Wt^T + b.  n-split 8 x k-split 2. ----
    int ni = w & 7;
    int kh = w >> 3;
    int n0b = ni * 8;
    int kbase = kh * 256;

    float acc2[4] = {0.f, 0.f, 0.f, 0.f};
    const uint2* aP0 = (const uint2*)(Av + g * SAV) + s4;
    const uint2* aP1 = (const uint2*)(Av + (g + 8) * SAV) + s4;
    const uint2* wR  = (const uint2*)(g_Wt + (size_t)f * DOUT * NK + (size_t)(n0b + g) * NK) + s4;
#pragma unroll 16
    for (int k0 = kbase; k0 < kbase + 256; k0 += 8) {
        int ki = k0 >> 1;
        uint2 a02 = aP0[ki], a13 = aP1[ki];
        uint2 b01 = __ldg(&wR[ki]);
        mma8(acc2, a02.x, a13.x, a02.y, a13.y, b01.x, b01.y);
    }
    __syncthreads();   // Ksm dead -> red
    if (kh == 1) {
        float* r = red + (ni * 32 + lane) * 4;
        r[0] = acc2[0]; r[1] = acc2[1]; r[2] = acc2[2]; r[3] = acc2[3];
    }
    __syncthreads();
    if (kh == 0) {
        const float* r = red + (ni * 32 + lane) * 4;
        acc2[0] += r[0]; acc2[1] += r[1]; acc2[2] += r[2]; acc2[3] += r[3];

        int tA2 = t0 + g, tB2 = tA2 + 8;
        int oc = n0b + 2 * s4;
        float2 ba = __ldg((const float2*)(Bv + ((size_t)(f * NT + tA2)) * DOUT + oc));
        float2 bb = __ldg((const float2*)(Bv + ((size_t)(f * NT + tB2)) * DOUT + oc));
        *(float2*)(Out + ((size_t)(bf * NT + tA2)) * DOUT + oc) =
            make_float2(acc2[0] + ba.x, acc2[1] + ba.y);
        *(float2*)(Out + ((size_t)(bf * NT + tB2)) * DOUT + oc) =
            make_float2(acc2[2] + bb.x, acc2[3] + bb.y);
    }
}

// ---------------------------------------------------------------------------
extern "C" void kernel_launch(void* const* d_in, const int* in_sizes, int n_in,
                              void* d_out, int out_size)
{
    const float* X     = (const float*)d_in[0];
    const float* ac    = (const float*)d_in[1];
    const float* alpha = (const float*)d_in[2];
    const float* Wq    = (const float*)d_in[3];
    const float* Wk    = (const float*)d_in[4];
    const float* wkey  = (const float*)d_in[5];
    const float* u     = (const float*)d_in[6];
    const float* W     = (const float*)d_in[7];
    const float* Bv    = (const float*)d_in[8];
    float* Out = (float*)d_out;

    cudaFuncSetAttribute(attn_kernel, cudaFuncAttributeMaxDynamicSharedMemorySize, K2_BYTES);

    pre_kernel<<<QK_BLOCKS + XT_BLOCKS + WT_BLOCKS, 256, 64 * 65 * 4>>>(X, Wq, Wk, W);
    attn_kernel<<<BF * 16, 512, K2_BYTES>>>(ac, alpha, wkey, u, Bv, Out);
}